// round 12
// baseline (speedup 1.0000x reference)
#include <cuda_runtime.h>
#include <cuda_bf16.h>
#include <math.h>
#include <stdint.h>

#define BB 1024
#define TT 256
#define CC 384
#define HH 64

// ---------------------------------------------------------------------------
// Device scratch (no allocations allowed)
// ---------------------------------------------------------------------------
__device__ float g_q[BB * TT * HH];
__device__ float g_k[BB * TT * HH];
__device__ float g_v[BB * TT * HH];
// Pre-swizzled SMEM image of W^T bf16 hi/lo per 64-wide K chunk:
// [6 chunks][hi 24576 B | lo 24576 B]; within each: [k 0..63][n-chunk 0..23]
// 16B chunks, chunk index swizzled: c' = (c & ~7) | ((c ^ k) & 7)
__device__ unsigned char g_wb[6 * 2 * 24576];

// ---------------------------------------------------------------------------
// helpers
// ---------------------------------------------------------------------------
__device__ __forceinline__ uint32_t smem_u32(const void* p) {
    uint32_t a;
    asm("{ .reg .u64 t; cvta.to.shared.u64 t, %1; cvt.u32.u64 %0, t; }"
        : "=r"(a) : "l"(p));
    return a;
}

__device__ __forceinline__ void ldsm_x4(uint32_t r[4], uint32_t addr) {
    asm volatile("ldmatrix.sync.aligned.m8n8.x4.shared.b16 {%0,%1,%2,%3}, [%4];"
                 : "=r"(r[0]), "=r"(r[1]), "=r"(r[2]), "=r"(r[3]) : "r"(addr));
}

__device__ __forceinline__ void ldsm_x4_trans(uint32_t r[4], uint32_t addr) {
    asm volatile("ldmatrix.sync.aligned.m8n8.x4.trans.shared.b16 {%0,%1,%2,%3}, [%4];"
                 : "=r"(r[0]), "=r"(r[1]), "=r"(r[2]), "=r"(r[3]) : "r"(addr));
}

__device__ __forceinline__ void mma_bf16(float c[4], const uint32_t a[4],
                                         const uint32_t b[2]) {
    asm volatile(
        "mma.sync.aligned.m16n8k16.row.col.f32.bf16.bf16.f32 "
        "{%0,%1,%2,%3}, {%4,%5,%6,%7}, {%8,%9}, {%0,%1,%2,%3};"
        : "+f"(c[0]), "+f"(c[1]), "+f"(c[2]), "+f"(c[3])
        : "r"(a[0]), "r"(a[1]), "r"(a[2]), "r"(a[3]), "r"(b[0]), "r"(b[1]));
}

__device__ __forceinline__ uint32_t pack_bf16(float a, float b) {
    __nv_bfloat162 t = __floats2bfloat162_rn(a, b);
    return *reinterpret_cast<uint32_t*>(&t);
}

// ---------------------------------------------------------------------------
// Setup: build the pre-swizzled W^T bf16 hi/lo image.
// n = mat*64 + h (mat 0:q, 1:k, 2:v). 6*64*192 = 73728 elements.
// ---------------------------------------------------------------------------
__global__ void setup_wb_kernel(const float* __restrict__ Wk,
                                const float* __restrict__ Wq,
                                const float* __restrict__ Wv)
{
    int idx = blockIdx.x * 256 + threadIdx.x;
    if (idx >= 6 * 64 * 192) return;
    int ck  = idx / (64 * 192);
    int rem = idx % (64 * 192);
    int k   = rem / 192;
    int n   = rem % 192;
    int mat = n >> 6, h = n & 63;
    const float* W = (mat == 0) ? Wq : (mat == 1) ? Wk : Wv;
    float v = W[(size_t)(ck * 64 + k) * HH + h];
    __nv_bfloat16 hi = __float2bfloat16(v);
    __nv_bfloat16 lo = __float2bfloat16(v - __bfloat162float(hi));
    int c  = n >> 3;
    int cs = (c & ~7) | ((c ^ k) & 7);
    uint32_t off = (uint32_t)k * 384u + (uint32_t)cs * 16u + (uint32_t)(n & 7) * 2u;
    unsigned char* base = g_wb + (size_t)ck * 49152;
    *reinterpret_cast<__nv_bfloat16*>(base + off)         = hi;
    *reinterpret_cast<__nv_bfloat16*>(base + 24576 + off) = lo;
}

// ---------------------------------------------------------------------------
// QKV projection via mma.sync bf16 split (3 passes, fp32 accumulate).
// CTA: M=128, N=192, K=384 in 6 chunks of 64. 256 threads = 8 warps (4m x 2n).
// Warp tile: 32m x 96n -> acc[2][12][4].
// ---------------------------------------------------------------------------
#define SM_A_HI  0
#define SM_A_LO  16384
#define SM_B_HI  32768
#define SM_B_LO  57344
#define SM_TOTAL 81920

__global__ __launch_bounds__(256) void qkv_mma_kernel(const float* __restrict__ x)
{
    extern __shared__ char smem[];
    const uint32_t sb = smem_u32(smem);
    const int tid  = threadIdx.x;
    const int wid  = tid >> 5;
    const int lane = tid & 31;
    const int m0   = blockIdx.x * 128;
    const int wm   = wid & 3;    // m offset 32*wm
    const int wn   = wid >> 2;   // n offset 96*wn

    float acc[2][12][4];
#pragma unroll
    for (int i = 0; i < 2; ++i)
#pragma unroll
        for (int j = 0; j < 12; ++j)
#pragma unroll
            for (int r = 0; r < 4; ++r) acc[i][j][r] = 0.0f;

    // A staging assignment: thread handles row r8 = tid>>1, k-half hf = tid&1
    const int r8 = tid >> 1;
    const int hf = tid & 1;
    const float* xrow = x + (size_t)(m0 + r8) * CC + hf * 32;

    // precomputed ldmatrix smem addresses (invariant over chunks except kk)
    // A: row = wm*32 + t16*16 + (lane&15), c8 = kk*2 + (lane>>4), swizzle c8^(row&7)
    const int a_row0 = wm * 32 + (lane & 15);
    const int a_chi  = lane >> 4;
    // B: k = kk*16 + (lane&15), c = (wn*96 + nt*16)>>3 + (lane>>4)
    const int b_k0   = lane & 15;

    for (int ck = 0; ck < 6; ++ck) {
        // --- stage A: load x chunk, convert to bf16 hi/lo, store swizzled ---
        {
            const float4* p = (const float4*)(xrow + ck * 64);
#pragma unroll
            for (int jj = 0; jj < 4; ++jj) {
                float4 u = p[2 * jj];
                float4 w = p[2 * jj + 1];
                float f0 = u.x, f1 = u.y, f2 = u.z, f3 = u.w;
                float f4 = w.x, f5 = w.y, f6 = w.z, f7 = w.w;
                float h0 = __bfloat162float(__float2bfloat16(f0));
                float h1 = __bfloat162float(__float2bfloat16(f1));
                float h2 = __bfloat162float(__float2bfloat16(f2));
                float h3 = __bfloat162float(__float2bfloat16(f3));
                float h4 = __bfloat162float(__float2bfloat16(f4));
                float h5 = __bfloat162float(__float2bfloat16(f5));
                float h6 = __bfloat162float(__float2bfloat16(f6));
                float h7 = __bfloat162float(__float2bfloat16(f7));
                uint4 hv, lv;
                hv.x = pack_bf16(h0, h1); hv.y = pack_bf16(h2, h3);
                hv.z = pack_bf16(h4, h5); hv.w = pack_bf16(h6, h7);
                lv.x = pack_bf16(f0 - h0, f1 - h1); lv.y = pack_bf16(f2 - h2, f3 - h3);
                lv.z = pack_bf16(f4 - h4, f5 - h5); lv.w = pack_bf16(f6 - h6, f7 - h7);
                int c8 = hf * 4 + jj;
                uint32_t off = (uint32_t)r8 * 128u + (uint32_t)((c8 ^ (r8 & 7)) * 16);
                *reinterpret_cast<uint4*>(smem + SM_A_HI + off) = hv;
                *reinterpret_cast<uint4*>(smem + SM_A_LO + off) = lv;
            }
        }
        // --- stage B: copy pre-swizzled image (hi+lo = 48 KB) ---
        {
            const uint4* src = reinterpret_cast<const uint4*>(g_wb + (size_t)ck * 49152);
            uint4* dst = reinterpret_cast<uint4*>(smem + SM_B_HI);
#pragma unroll
            for (int i = 0; i < 12; ++i) dst[tid + i * 256] = src[tid + i * 256];
        }
        __syncthreads();

        // --- compute: 4 k16 steps ---
#pragma unroll 1
        for (int kk = 0; kk < 4; ++kk) {
            uint32_t ah[2][4], al[2][4];
#pragma unroll
            for (int t16 = 0; t16 < 2; ++t16) {
                int row = a_row0 + t16 * 16;
                int c8  = kk * 2 + a_chi;
                uint32_t off = (uint32_t)row * 128u + (uint32_t)((c8 ^ (row & 7)) * 16);
                ldsm_x4(ah[t16], sb + SM_A_HI + off);
                ldsm_x4(al[t16], sb + SM_A_LO + off);
            }
            uint32_t bh[12][2], bl[12][2];
#pragma unroll
            for (int nt = 0; nt < 6; ++nt) {
                int k = kk * 16 + b_k0;
                int c = ((wn * 96 + nt * 16) >> 3) + (lane >> 4);
                int cs = (c & ~7) | ((c ^ k) & 7);
                uint32_t off = (uint32_t)k * 384u + (uint32_t)cs * 16u;
                uint32_t t[4];
                ldsm_x4_trans(t, sb + SM_B_HI + off);
                bh[2*nt][0] = t[0]; bh[2*nt][1] = t[1];
                bh[2*nt+1][0] = t[2]; bh[2*nt+1][1] = t[3];
                ldsm_x4_trans(t, sb + SM_B_LO + off);
                bl[2*nt][0] = t[0]; bl[2*nt][1] = t[1];
                bl[2*nt+1][0] = t[2]; bl[2*nt+1][1] = t[3];
            }
#pragma unroll
            for (int t16 = 0; t16 < 2; ++t16)
#pragma unroll
                for (int nt8 = 0; nt8 < 12; ++nt8) {
                    mma_bf16(acc[t16][nt8], ah[t16], bh[nt8]);  // hi*hi
                    mma_bf16(acc[t16][nt8], ah[t16], bl[nt8]);  // hi*lo
                    mma_bf16(acc[t16][nt8], al[t16], bh[nt8]);  // lo*hi
                }
        }
        __syncthreads();
    }

    // --- epilogue: write fp32 results to g_q / g_k / g_v ---
#pragma unroll
    for (int t16 = 0; t16 < 2; ++t16) {
        int row0 = m0 + wm * 32 + t16 * 16 + (lane >> 2);
#pragma unroll
        for (int nt8 = 0; nt8 < 12; ++nt8) {
            int col = wn * 96 + nt8 * 8 + (lane & 3) * 2;
            int mat = col >> 6;
            int h   = col & 63;
            float* dst = (mat == 0) ? g_q : (mat == 1) ? g_k : g_v;
            *reinterpret_cast<float2*>(dst + (size_t)row0 * HH + h) =
                make_float2(acc[t16][nt8][0], acc[t16][nt8][1]);
            *reinterpret_cast<float2*>(dst + (size_t)(row0 + 8) * HH + h) =
                make_float2(acc[t16][nt8][2], acc[t16][nt8][3]);
        }
    }
}

// ---------------------------------------------------------------------------
// Attention: one CTA per batch, K/V resident in SMEM, one thread per query row.
// Warp pairs on each SMSP get complementary triangle chunks (sum = 288).
// ---------------------------------------------------------------------------
__global__ __launch_bounds__(256) void attn_kernel(float* __restrict__ out)
{
    extern __shared__ float sm[];
    float* Ks = sm;                 // [256][64]
    float* Vs = sm + TT * HH;       // [256][64]

    const int b    = blockIdx.x;
    const int tid  = threadIdx.x;
    const int wid  = tid >> 5;
    const int lane = tid & 31;
    const size_t base = (size_t)b * TT * HH;

    const int chunk = (wid < 4) ? wid : (11 - wid);
    const int row   = chunk * 32 + lane;

    {
        const float4* kg = (const float4*)(g_k + base);
        const float4* vg = (const float4*)(g_v + base);
        float4* ks4 = (float4*)Ks;
        float4* vs4 = (float4*)Vs;
#pragma unroll
        for (int i = 0; i < 16; ++i) {
            ks4[tid + i * 256] = kg[tid + i * 256];
            vs4[tid + i * 256] = vg[tid + i * 256];
        }
    }
    __syncthreads();

    float qv[64];
    {
        const float4* qg = (const float4*)(g_q + base + (size_t)row * HH);
#pragma unroll
        for (int i = 0; i < 16; ++i) {
            float4 t4 = qg[i];
            qv[4*i+0] = t4.x; qv[4*i+1] = t4.y;
            qv[4*i+2] = t4.z; qv[4*i+3] = t4.w;
        }
    }

    float acc[64];
#pragma unroll
    for (int d = 0; d < 64; ++d) acc[d] = 0.0f;

    float m = -INFINITY;
    float l = 0.0f;
    const float scale = 0.05103103630798287f;  // 384^-0.5 (embed dim C)

    for (int j = 0; j <= row; ++j) {
        const float4* krow = (const float4*)(Ks + j * HH);
        float s0 = 0.f, s1 = 0.f, s2 = 0.f, s3 = 0.f;
#pragma unroll
        for (int i = 0; i < 16; ++i) {
            float4 k4 = krow[i];
            s0 = fmaf(qv[4*i+0], k4.x, s0);
            s1 = fmaf(qv[4*i+1], k4.y, s1);
            s2 = fmaf(qv[4*i+2], k4.z, s2);
            s3 = fmaf(qv[4*i+3], k4.w, s3);
        }
        float s = ((s0 + s1) + (s2 + s3)) * scale;

        if (s > m) {
            float corr = __expf(m - s);
            l *= corr;
#pragma unroll
            for (int d = 0; d < 64; ++d) acc[d] *= corr;
            m = s;
        }
        float p = __expf(s - m);
        l += p;

        const float4* vrow = (const float4*)(Vs + j * HH);
#pragma unroll
        for (int i = 0; i < 16; ++i) {
            float4 v4 = vrow[i];
            acc[4*i+0] = fmaf(p, v4.x, acc[4*i+0]);
            acc[4*i+1] = fmaf(p, v4.y, acc[4*i+1]);
            acc[4*i+2] = fmaf(p, v4.z, acc[4*i+2]);
            acc[4*i+3] = fmaf(p, v4.w, acc[4*i+3]);
        }
    }

    const float inv = 1.0f / l;
    float4* og = (float4*)(out + base + (size_t)row * HH);
#pragma unroll
    for (int i = 0; i < 16; ++i) {
        og[i] = make_float4(acc[4*i+0] * inv, acc[4*i+1] * inv,
                            acc[4*i+2] * inv, acc[4*i+3] * inv);
    }
}

// ---------------------------------------------------------------------------
extern "C" void kernel_launch(void* const* d_in, const int* in_sizes, int n_in,
                              void* d_out, int out_size)
{
    (void)in_sizes; (void)n_in; (void)out_size;
    const float* x  = (const float*)d_in[0];
    const float* Wk = (const float*)d_in[1];
    const float* Wq = (const float*)d_in[2];
    const float* Wv = (const float*)d_in[3];
    float* out = (float*)d_out;

    setup_wb_kernel<<<(6 * 64 * 192 + 255) / 256, 256>>>(Wk, Wq, Wv);

    cudaFuncSetAttribute(qkv_mma_kernel, cudaFuncAttributeMaxDynamicSharedMemorySize,
                         SM_TOTAL);
    qkv_mma_kernel<<<(BB * TT) / 128, 256, SM_TOTAL>>>(x);

    cudaFuncSetAttribute(attn_kernel, cudaFuncAttributeMaxDynamicSharedMemorySize,
                         2 * TT * HH * (int)sizeof(float));
    attn_kernel<<<BB, 256, 2 * TT * HH * sizeof(float)>>>(out);
}

// round 13
// speedup vs baseline: 1.5910x; 1.5910x over previous
#include <cuda_runtime.h>
#include <cuda_bf16.h>
#include <math.h>
#include <stdint.h>

#define BB 1024
#define TT 256
#define CC 384
#define HH 64

// ---------------------------------------------------------------------------
// Device scratch (no allocations allowed)
// ---------------------------------------------------------------------------
__device__ float g_q[BB * TT * HH];
__device__ float g_k[BB * TT * HH];
__device__ float g_v[BB * TT * HH];
// Pre-swizzled SMEM image of W^T bf16 hi/lo per 64-wide K chunk
__device__ unsigned char g_wb[6 * 2 * 24576];

// ---------------------------------------------------------------------------
// helpers
// ---------------------------------------------------------------------------
__device__ __forceinline__ uint32_t smem_u32(const void* p) {
    uint32_t a;
    asm("{ .reg .u64 t; cvta.to.shared.u64 t, %1; cvt.u32.u64 %0, t; }"
        : "=r"(a) : "l"(p));
    return a;
}

__device__ __forceinline__ void ldsm_x4(uint32_t r[4], uint32_t addr) {
    asm volatile("ldmatrix.sync.aligned.m8n8.x4.shared.b16 {%0,%1,%2,%3}, [%4];"
                 : "=r"(r[0]), "=r"(r[1]), "=r"(r[2]), "=r"(r[3]) : "r"(addr));
}

__device__ __forceinline__ void ldsm_x4_trans(uint32_t r[4], uint32_t addr) {
    asm volatile("ldmatrix.sync.aligned.m8n8.x4.trans.shared.b16 {%0,%1,%2,%3}, [%4];"
                 : "=r"(r[0]), "=r"(r[1]), "=r"(r[2]), "=r"(r[3]) : "r"(addr));
}

__device__ __forceinline__ void mma_bf16(float c[4], const uint32_t a[4],
                                         const uint32_t b[2]) {
    asm volatile(
        "mma.sync.aligned.m16n8k16.row.col.f32.bf16.bf16.f32 "
        "{%0,%1,%2,%3}, {%4,%5,%6,%7}, {%8,%9}, {%0,%1,%2,%3};"
        : "+f"(c[0]), "+f"(c[1]), "+f"(c[2]), "+f"(c[3])
        : "r"(a[0]), "r"(a[1]), "r"(a[2]), "r"(a[3]), "r"(b[0]), "r"(b[1]));
}

__device__ __forceinline__ uint32_t pack_bf16(float a, float b) {
    __nv_bfloat162 t = __floats2bfloat162_rn(a, b);
    return *reinterpret_cast<uint32_t*>(&t);
}

__device__ __forceinline__ float bf16_rt(float a) {   // round-trip through bf16
    return __bfloat162float(__float2bfloat16(a));
}

// ---------------------------------------------------------------------------
// Setup: pre-swizzled W^T bf16 hi/lo image (unchanged)
// ---------------------------------------------------------------------------
__global__ void setup_wb_kernel(const float* __restrict__ Wk,
                                const float* __restrict__ Wq,
                                const float* __restrict__ Wv)
{
    int idx = blockIdx.x * 256 + threadIdx.x;
    if (idx >= 6 * 64 * 192) return;
    int ck  = idx / (64 * 192);
    int rem = idx % (64 * 192);
    int k   = rem / 192;
    int n   = rem % 192;
    int mat = n >> 6, h = n & 63;
    const float* W = (mat == 0) ? Wq : (mat == 1) ? Wk : Wv;
    float v = W[(size_t)(ck * 64 + k) * HH + h];
    __nv_bfloat16 hi = __float2bfloat16(v);
    __nv_bfloat16 lo = __float2bfloat16(v - __bfloat162float(hi));
    int c  = n >> 3;
    int cs = (c & ~7) | ((c ^ k) & 7);
    uint32_t off = (uint32_t)k * 384u + (uint32_t)cs * 16u + (uint32_t)(n & 7) * 2u;
    unsigned char* base = g_wb + (size_t)ck * 49152;
    *reinterpret_cast<__nv_bfloat16*>(base + off)         = hi;
    *reinterpret_cast<__nv_bfloat16*>(base + 24576 + off) = lo;
}

// ---------------------------------------------------------------------------
// QKV projection via mma.sync bf16 split (unchanged from passing R3)
// ---------------------------------------------------------------------------
#define SM_A_HI  0
#define SM_A_LO  16384
#define SM_B_HI  32768
#define SM_B_LO  57344
#define SM_TOTAL 81920

__global__ __launch_bounds__(256) void qkv_mma_kernel(const float* __restrict__ x)
{
    extern __shared__ char smem[];
    const uint32_t sb = smem_u32(smem);
    const int tid  = threadIdx.x;
    const int wid  = tid >> 5;
    const int lane = tid & 31;
    const int m0   = blockIdx.x * 128;
    const int wm   = wid & 3;
    const int wn   = wid >> 2;

    float acc[2][12][4];
#pragma unroll
    for (int i = 0; i < 2; ++i)
#pragma unroll
        for (int j = 0; j < 12; ++j)
#pragma unroll
            for (int r = 0; r < 4; ++r) acc[i][j][r] = 0.0f;

    const int r8 = tid >> 1;
    const int hf = tid & 1;
    const float* xrow = x + (size_t)(m0 + r8) * CC + hf * 32;

    const int a_row0 = wm * 32 + (lane & 15);
    const int a_chi  = lane >> 4;
    const int b_k0   = lane & 15;

    for (int ck = 0; ck < 6; ++ck) {
        {
            const float4* p = (const float4*)(xrow + ck * 64);
#pragma unroll
            for (int jj = 0; jj < 4; ++jj) {
                float4 u = p[2 * jj];
                float4 w = p[2 * jj + 1];
                float f0 = u.x, f1 = u.y, f2 = u.z, f3 = u.w;
                float f4 = w.x, f5 = w.y, f6 = w.z, f7 = w.w;
                float h0 = bf16_rt(f0), h1 = bf16_rt(f1), h2 = bf16_rt(f2), h3 = bf16_rt(f3);
                float h4 = bf16_rt(f4), h5 = bf16_rt(f5), h6 = bf16_rt(f6), h7 = bf16_rt(f7);
                uint4 hv, lv;
                hv.x = pack_bf16(h0, h1); hv.y = pack_bf16(h2, h3);
                hv.z = pack_bf16(h4, h5); hv.w = pack_bf16(h6, h7);
                lv.x = pack_bf16(f0 - h0, f1 - h1); lv.y = pack_bf16(f2 - h2, f3 - h3);
                lv.z = pack_bf16(f4 - h4, f5 - h5); lv.w = pack_bf16(f6 - h6, f7 - h7);
                int c8 = hf * 4 + jj;
                uint32_t off = (uint32_t)r8 * 128u + (uint32_t)((c8 ^ (r8 & 7)) * 16);
                *reinterpret_cast<uint4*>(smem + SM_A_HI + off) = hv;
                *reinterpret_cast<uint4*>(smem + SM_A_LO + off) = lv;
            }
        }
        {
            const uint4* src = reinterpret_cast<const uint4*>(g_wb + (size_t)ck * 49152);
            uint4* dst = reinterpret_cast<uint4*>(smem + SM_B_HI);
#pragma unroll
            for (int i = 0; i < 12; ++i) dst[tid + i * 256] = src[tid + i * 256];
        }
        __syncthreads();

#pragma unroll 1
        for (int kk = 0; kk < 4; ++kk) {
            uint32_t ah[2][4], al[2][4];
#pragma unroll
            for (int t16 = 0; t16 < 2; ++t16) {
                int row = a_row0 + t16 * 16;
                int c8  = kk * 2 + a_chi;
                uint32_t off = (uint32_t)row * 128u + (uint32_t)((c8 ^ (row & 7)) * 16);
                ldsm_x4(ah[t16], sb + SM_A_HI + off);
                ldsm_x4(al[t16], sb + SM_A_LO + off);
            }
            uint32_t bh[12][2], bl[12][2];
#pragma unroll
            for (int nt = 0; nt < 6; ++nt) {
                int k = kk * 16 + b_k0;
                int c = ((wn * 96 + nt * 16) >> 3) + (lane >> 4);
                int cs = (c & ~7) | ((c ^ k) & 7);
                uint32_t off = (uint32_t)k * 384u + (uint32_t)cs * 16u;
                uint32_t t[4];
                ldsm_x4_trans(t, sb + SM_B_HI + off);
                bh[2*nt][0] = t[0]; bh[2*nt][1] = t[1];
                bh[2*nt+1][0] = t[2]; bh[2*nt+1][1] = t[3];
                ldsm_x4_trans(t, sb + SM_B_LO + off);
                bl[2*nt][0] = t[0]; bl[2*nt][1] = t[1];
                bl[2*nt+1][0] = t[2]; bl[2*nt+1][1] = t[3];
            }
#pragma unroll
            for (int t16 = 0; t16 < 2; ++t16)
#pragma unroll
                for (int nt8 = 0; nt8 < 12; ++nt8) {
                    mma_bf16(acc[t16][nt8], ah[t16], bh[nt8]);
                    mma_bf16(acc[t16][nt8], ah[t16], bl[nt8]);
                    mma_bf16(acc[t16][nt8], al[t16], bh[nt8]);
                }
        }
        __syncthreads();
    }

#pragma unroll
    for (int t16 = 0; t16 < 2; ++t16) {
        int row0 = m0 + wm * 32 + t16 * 16 + (lane >> 2);
#pragma unroll
        for (int nt8 = 0; nt8 < 12; ++nt8) {
            int col = wn * 96 + nt8 * 8 + (lane & 3) * 2;
            int mat = col >> 6;
            int h   = col & 63;
            float* dst = (mat == 0) ? g_q : (mat == 1) ? g_k : g_v;
            *reinterpret_cast<float2*>(dst + (size_t)row0 * HH + h) =
                make_float2(acc[t16][nt8][0], acc[t16][nt8][1]);
            *reinterpret_cast<float2*>(dst + (size_t)(row0 + 8) * HH + h) =
                make_float2(acc[t16][nt8][2], acc[t16][nt8][3]);
        }
    }
}

// ---------------------------------------------------------------------------
// Tensor-core flash attention. One CTA = one batch, 8 warps, 32 q-rows each.
// K,V in SMEM as bf16 hi/lo ([key][64] rows, 128B, XOR-16B-chunk swizzle).
// QK: 2 passes (q_hi*k_hi + q_hi*k_lo). PV: 3 passes (ph*vh + ph*vl + pl*vh).
// ---------------------------------------------------------------------------
#define SM_K_HI  0
#define SM_K_LO  32768
#define SM_V_HI  65536
#define SM_V_LO  98304
#define SM_ATT   131072

__global__ __launch_bounds__(256) void attn_mma_kernel(float* __restrict__ out)
{
    extern __shared__ char smem[];
    const uint32_t sb = smem_u32(smem);
    const int b    = blockIdx.x;
    const int tid  = threadIdx.x;
    const int wid  = tid >> 5;
    const int lane = tid & 31;
    const size_t base = (size_t)b * TT * HH;

    // ---- stage K and V (fp32 -> bf16 hi/lo, swizzled) ----
    {
        const float4* kg = (const float4*)(g_k + base);
        const float4* vg = (const float4*)(g_v + base);
#pragma unroll
        for (int p = 0; p < 16; ++p) {
            int idx = tid + p * 256;            // 0..4095
            int key = idx >> 4;
            int j   = idx & 15;                 // float4 index within row
            uint32_t off = (uint32_t)key * 128u
                         + (uint32_t)((((j >> 1) ^ key) & 7) * 16)
                         + (uint32_t)((j & 1) * 8);
            float4 f = kg[idx];
            float hx = bf16_rt(f.x), hy = bf16_rt(f.y), hz = bf16_rt(f.z), hw = bf16_rt(f.w);
            *(uint2*)(smem + SM_K_HI + off) =
                make_uint2(pack_bf16(f.x, f.y), pack_bf16(f.z, f.w));
            *(uint2*)(smem + SM_K_LO + off) =
                make_uint2(pack_bf16(f.x - hx, f.y - hy), pack_bf16(f.z - hz, f.w - hw));
            f = vg[idx];
            hx = bf16_rt(f.x); hy = bf16_rt(f.y); hz = bf16_rt(f.z); hw = bf16_rt(f.w);
            *(uint2*)(smem + SM_V_HI + off) =
                make_uint2(pack_bf16(f.x, f.y), pack_bf16(f.z, f.w));
            *(uint2*)(smem + SM_V_LO + off) =
                make_uint2(pack_bf16(f.x - hx, f.y - hy), pack_bf16(f.z - hz, f.w - hw));
        }
    }
    __syncthreads();

    // SMSP-balanced triangle: chunks (0,7),(1,6),(2,5),(3,4) pair on SMSPs
    const int chunk = (wid < 4) ? wid : (11 - wid);
    const int q0    = chunk * 32;
    const float scale = 0.05103103630798287f;   // 384^-0.5 (embed dim C)

    // ---- Q A-fragments (hi only, scale folded) ----
    uint32_t qh[2][4][4];
#pragma unroll
    for (int i = 0; i < 2; ++i)
#pragma unroll
        for (int kt = 0; kt < 4; ++kt) {
            const float* qp = g_q + base
                + (size_t)(q0 + 16 * i + (lane >> 2)) * HH + kt * 16 + 2 * (lane & 3);
            float2 v0 = *(const float2*)qp;
            float2 v1 = *(const float2*)(qp + 8 * HH);
            float2 v2 = *(const float2*)(qp + 8);
            float2 v3 = *(const float2*)(qp + 8 * HH + 8);
            qh[i][kt][0] = pack_bf16(v0.x * scale, v0.y * scale);
            qh[i][kt][1] = pack_bf16(v1.x * scale, v1.y * scale);
            qh[i][kt][2] = pack_bf16(v2.x * scale, v2.y * scale);
            qh[i][kt][3] = pack_bf16(v3.x * scale, v3.y * scale);
        }

    float o[2][8][4];
#pragma unroll
    for (int i = 0; i < 2; ++i)
#pragma unroll
        for (int j = 0; j < 8; ++j)
#pragma unroll
            for (int r = 0; r < 4; ++r) o[i][j][r] = 0.0f;

    float mrow[2][2] = {{-INFINITY, -INFINITY}, {-INFINITY, -INFINITY}};
    float lrow[2][2] = {{0.0f, 0.0f}, {0.0f, 0.0f}};

    for (int kb = 0; kb <= chunk; ++kb) {
        // ---- S = Q K^T (scaled) ----
        float sc[2][4][4];
#pragma unroll
        for (int i = 0; i < 2; ++i)
#pragma unroll
            for (int j = 0; j < 4; ++j)
#pragma unroll
                for (int r = 0; r < 4; ++r) sc[i][j][r] = 0.0f;

#pragma unroll
        for (int kt = 0; kt < 4; ++kt) {
            uint32_t kbh[4][2], kbl[4][2];
#pragma unroll
            for (int jn = 0; jn < 4; ++jn) {
                int key = kb * 32 + jn * 8 + (lane >> 2);
                uint32_t rowb = (uint32_t)key * 128u + (uint32_t)(lane & 3) * 4u;
                uint32_t c0 = (uint32_t)(((kt * 2)     ^ (key & 7)) * 16);
                uint32_t c1 = (uint32_t)(((kt * 2 + 1) ^ (key & 7)) * 16);
                kbh[jn][0] = *(const uint32_t*)(smem + SM_K_HI + rowb + c0);
                kbh[jn][1] = *(const uint32_t*)(smem + SM_K_HI + rowb + c1);
                kbl[jn][0] = *(const uint32_t*)(smem + SM_K_LO + rowb + c0);
                kbl[jn][1] = *(const uint32_t*)(smem + SM_K_LO + rowb + c1);
            }
#pragma unroll
            for (int i = 0; i < 2; ++i)
#pragma unroll
                for (int jn = 0; jn < 4; ++jn) {
                    mma_bf16(sc[i][jn], qh[i][kt], kbh[jn]);
                    mma_bf16(sc[i][jn], qh[i][kt], kbl[jn]);
                }
        }

        // ---- causal mask on diagonal block ----
        if (kb == chunk) {
#pragma unroll
            for (int i = 0; i < 2; ++i) {
                int rl = 16 * i + (lane >> 2);
#pragma unroll
                for (int jn = 0; jn < 4; ++jn) {
                    int k0 = jn * 8 + 2 * (lane & 3);
                    if (k0     > rl    ) sc[i][jn][0] = -INFINITY;
                    if (k0 + 1 > rl    ) sc[i][jn][1] = -INFINITY;
                    if (k0     > rl + 8) sc[i][jn][2] = -INFINITY;
                    if (k0 + 1 > rl + 8) sc[i][jn][3] = -INFINITY;
                }
            }
        }

        // ---- online softmax + P pack ----
        uint32_t ph[2][2][4], pl[2][2][4];
#pragma unroll
        for (int i = 0; i < 2; ++i) {
            float mx0 = fmaxf(fmaxf(sc[i][0][0], sc[i][0][1]),
                              fmaxf(sc[i][1][0], sc[i][1][1]));
            mx0 = fmaxf(mx0, fmaxf(fmaxf(sc[i][2][0], sc[i][2][1]),
                                   fmaxf(sc[i][3][0], sc[i][3][1])));
            float mx1 = fmaxf(fmaxf(sc[i][0][2], sc[i][0][3]),
                              fmaxf(sc[i][1][2], sc[i][1][3]));
            mx1 = fmaxf(mx1, fmaxf(fmaxf(sc[i][2][2], sc[i][2][3]),
                                   fmaxf(sc[i][3][2], sc[i][3][3])));
            mx0 = fmaxf(mx0, __shfl_xor_sync(0xffffffffu, mx0, 1));
            mx0 = fmaxf(mx0, __shfl_xor_sync(0xffffffffu, mx0, 2));
            mx1 = fmaxf(mx1, __shfl_xor_sync(0xffffffffu, mx1, 1));
            mx1 = fmaxf(mx1, __shfl_xor_sync(0xffffffffu, mx1, 2));
            float nm0 = fmaxf(mrow[i][0], mx0);
            float nm1 = fmaxf(mrow[i][1], mx1);
            float cr0 = __expf(mrow[i][0] - nm0);
            float cr1 = __expf(mrow[i][1] - nm1);
            mrow[i][0] = nm0; mrow[i][1] = nm1;
            float rs0 = 0.0f, rs1 = 0.0f;
#pragma unroll
            for (int jn = 0; jn < 4; ++jn) {
                sc[i][jn][0] = __expf(sc[i][jn][0] - nm0); rs0 += sc[i][jn][0];
                sc[i][jn][1] = __expf(sc[i][jn][1] - nm0); rs0 += sc[i][jn][1];
                sc[i][jn][2] = __expf(sc[i][jn][2] - nm1); rs1 += sc[i][jn][2];
                sc[i][jn][3] = __expf(sc[i][jn][3] - nm1); rs1 += sc[i][jn][3];
            }
            rs0 += __shfl_xor_sync(0xffffffffu, rs0, 1);
            rs0 += __shfl_xor_sync(0xffffffffu, rs0, 2);
            rs1 += __shfl_xor_sync(0xffffffffu, rs1, 1);
            rs1 += __shfl_xor_sync(0xffffffffu, rs1, 2);
            lrow[i][0] = lrow[i][0] * cr0 + rs0;
            lrow[i][1] = lrow[i][1] * cr1 + rs1;
#pragma unroll
            for (int jd = 0; jd < 8; ++jd) {
                o[i][jd][0] *= cr0; o[i][jd][1] *= cr0;
                o[i][jd][2] *= cr1; o[i][jd][3] *= cr1;
            }
            // pack P accumulators straight into A-fragments (hi/lo split)
#pragma unroll
            for (int kp = 0; kp < 2; ++kp)
#pragma unroll
                for (int rr = 0; rr < 4; ++rr) {
                    int jt = 2 * kp + (rr >> 1);
                    int e  = (rr & 1) * 2;
                    float p0 = sc[i][jt][e], p1 = sc[i][jt][e + 1];
                    float h0 = bf16_rt(p0), h1 = bf16_rt(p1);
                    ph[i][kp][rr] = pack_bf16(p0, p1);
                    pl[i][kp][rr] = pack_bf16(p0 - h0, p1 - h1);
                }
        }

        // ---- O += P V ----
#pragma unroll
        for (int kp = 0; kp < 2; ++kp) {
            int keyr = kb * 32 + kp * 16 + (lane & 15);
#pragma unroll
            for (int g = 0; g < 4; ++g) {
                uint32_t cidx = (uint32_t)(((2 * g + (lane >> 4)) ^ keyr) & 7);
                uint32_t addr = sb + SM_V_HI + (uint32_t)keyr * 128u + cidx * 16u;
                uint32_t th[4], tl[4];
                ldsm_x4_trans(th, addr);
                ldsm_x4_trans(tl, addr + (SM_V_LO - SM_V_HI));
                uint32_t bh0[2] = {th[0], th[1]}, bh1[2] = {th[2], th[3]};
                uint32_t bl0[2] = {tl[0], tl[1]}, bl1[2] = {tl[2], tl[3]};
#pragma unroll
                for (int i = 0; i < 2; ++i) {
                    mma_bf16(o[i][2*g],     ph[i][kp], bh0);
                    mma_bf16(o[i][2*g],     ph[i][kp], bl0);
                    mma_bf16(o[i][2*g],     pl[i][kp], bh0);
                    mma_bf16(o[i][2*g+1],   ph[i][kp], bh1);
                    mma_bf16(o[i][2*g+1],   ph[i][kp], bl1);
                    mma_bf16(o[i][2*g+1],   pl[i][kp], bh1);
                }
            }
        }
    }

    // ---- epilogue: normalize and store ----
#pragma unroll
    for (int i = 0; i < 2; ++i) {
        float inv0 = 1.0f / lrow[i][0];
        float inv1 = 1.0f / lrow[i][1];
        int row = q0 + 16 * i + (lane >> 2);
        float* op = out + base + (size_t)row * HH + 2 * (lane & 3);
#pragma unroll
        for (int jd = 0; jd < 8; ++jd) {
            *(float2*)(op + jd * 8) =
                make_float2(o[i][jd][0] * inv0, o[i][jd][1] * inv0);
            *(float2*)(op + 8 * HH + jd * 8) =
                make_float2(o[i][jd][2] * inv1, o[i][jd][3] * inv1);
        }
    }
}

// ---------------------------------------------------------------------------
extern "C" void kernel_launch(void* const* d_in, const int* in_sizes, int n_in,
                              void* d_out, int out_size)
{
    (void)in_sizes; (void)n_in; (void)out_size;
    const float* x  = (const float*)d_in[0];
    const float* Wk = (const float*)d_in[1];
    const float* Wq = (const float*)d_in[2];
    const float* Wv = (const float*)d_in[3];
    float* out = (float*)d_out;

    setup_wb_kernel<<<(6 * 64 * 192 + 255) / 256, 256>>>(Wk, Wq, Wv);

    cudaFuncSetAttribute(qkv_mma_kernel, cudaFuncAttributeMaxDynamicSharedMemorySize,
                         SM_TOTAL);
    qkv_mma_kernel<<<(BB * TT) / 128, 256, SM_TOTAL>>>(x);

    cudaFuncSetAttribute(attn_mma_kernel, cudaFuncAttributeMaxDynamicSharedMemorySize,
                         SM_ATT);
    attn_mma_kernel<<<BB, 256, SM_ATT>>>(out);
}

// round 14
// speedup vs baseline: 1.5911x; 1.0001x over previous
#include <cuda_runtime.h>
#include <cuda_bf16.h>
#include <math.h>
#include <stdint.h>

#define BB 1024
#define TT 256
#define CC 384
#define HH 64

// ---------------------------------------------------------------------------
// Device scratch (no allocations allowed)
// ---------------------------------------------------------------------------
__device__ float g_q[BB * TT * HH];
__device__ float g_k[BB * TT * HH];
__device__ float g_v[BB * TT * HH];
// Pre-swizzled SMEM image of W^T bf16 hi/lo per 64-wide K chunk
__device__ unsigned char g_wb[6 * 2 * 24576];

// ---------------------------------------------------------------------------
// helpers
// ---------------------------------------------------------------------------
__device__ __forceinline__ uint32_t smem_u32(const void* p) {
    uint32_t a;
    asm("{ .reg .u64 t; cvta.to.shared.u64 t, %1; cvt.u32.u64 %0, t; }"
        : "=r"(a) : "l"(p));
    return a;
}

__device__ __forceinline__ void ldsm_x4(uint32_t r[4], uint32_t addr) {
    asm volatile("ldmatrix.sync.aligned.m8n8.x4.shared.b16 {%0,%1,%2,%3}, [%4];"
                 : "=r"(r[0]), "=r"(r[1]), "=r"(r[2]), "=r"(r[3]) : "r"(addr));
}

__device__ __forceinline__ void ldsm_x4_trans(uint32_t r[4], uint32_t addr) {
    asm volatile("ldmatrix.sync.aligned.m8n8.x4.trans.shared.b16 {%0,%1,%2,%3}, [%4];"
                 : "=r"(r[0]), "=r"(r[1]), "=r"(r[2]), "=r"(r[3]) : "r"(addr));
}

__device__ __forceinline__ void mma_bf16(float c[4], const uint32_t a[4],
                                         const uint32_t b[2]) {
    asm volatile(
        "mma.sync.aligned.m16n8k16.row.col.f32.bf16.bf16.f32 "
        "{%0,%1,%2,%3}, {%4,%5,%6,%7}, {%8,%9}, {%0,%1,%2,%3};"
        : "+f"(c[0]), "+f"(c[1]), "+f"(c[2]), "+f"(c[3])
        : "r"(a[0]), "r"(a[1]), "r"(a[2]), "r"(a[3]), "r"(b[0]), "r"(b[1]));
}

__device__ __forceinline__ uint32_t pack_bf16(float a, float b) {
    __nv_bfloat162 t = __floats2bfloat162_rn(a, b);
    return *reinterpret_cast<uint32_t*>(&t);
}

__device__ __forceinline__ float bf16_rt(float a) {   // round-trip through bf16
    return __bfloat162float(__float2bfloat16(a));
}

// ---------------------------------------------------------------------------
// Setup: pre-swizzled W^T bf16 hi/lo image (unchanged)
// ---------------------------------------------------------------------------
__global__ void setup_wb_kernel(const float* __restrict__ Wk,
                                const float* __restrict__ Wq,
                                const float* __restrict__ Wv)
{
    int idx = blockIdx.x * 256 + threadIdx.x;
    if (idx >= 6 * 64 * 192) return;
    int ck  = idx / (64 * 192);
    int rem = idx % (64 * 192);
    int k   = rem / 192;
    int n   = rem % 192;
    int mat = n >> 6, h = n & 63;
    const float* W = (mat == 0) ? Wq : (mat == 1) ? Wk : Wv;
    float v = W[(size_t)(ck * 64 + k) * HH + h];
    __nv_bfloat16 hi = __float2bfloat16(v);
    __nv_bfloat16 lo = __float2bfloat16(v - __bfloat162float(hi));
    int c  = n >> 3;
    int cs = (c & ~7) | ((c ^ k) & 7);
    uint32_t off = (uint32_t)k * 384u + (uint32_t)cs * 16u + (uint32_t)(n & 7) * 2u;
    unsigned char* base = g_wb + (size_t)ck * 49152;
    *reinterpret_cast<__nv_bfloat16*>(base + off)         = hi;
    *reinterpret_cast<__nv_bfloat16*>(base + 24576 + off) = lo;
}

// ---------------------------------------------------------------------------
// QKV projection via mma.sync bf16 split (unchanged from passing R3)
// ---------------------------------------------------------------------------
#define SM_A_HI  0
#define SM_A_LO  16384
#define SM_B_HI  32768
#define SM_B_LO  57344
#define SM_TOTAL 81920

__global__ __launch_bounds__(256) void qkv_mma_kernel(const float* __restrict__ x)
{
    extern __shared__ char smem[];
    const uint32_t sb = smem_u32(smem);
    const int tid  = threadIdx.x;
    const int wid  = tid >> 5;
    const int lane = tid & 31;
    const int m0   = blockIdx.x * 128;
    const int wm   = wid & 3;
    const int wn   = wid >> 2;

    float acc[2][12][4];
#pragma unroll
    for (int i = 0; i < 2; ++i)
#pragma unroll
        for (int j = 0; j < 12; ++j)
#pragma unroll
            for (int r = 0; r < 4; ++r) acc[i][j][r] = 0.0f;

    const int r8 = tid >> 1;
    const int hf = tid & 1;
    const float* xrow = x + (size_t)(m0 + r8) * CC + hf * 32;

    const int a_row0 = wm * 32 + (lane & 15);
    const int a_chi  = lane >> 4;
    const int b_k0   = lane & 15;

    for (int ck = 0; ck < 6; ++ck) {
        {
            const float4* p = (const float4*)(xrow + ck * 64);
#pragma unroll
            for (int jj = 0; jj < 4; ++jj) {
                float4 u = p[2 * jj];
                float4 w = p[2 * jj + 1];
                float f0 = u.x, f1 = u.y, f2 = u.z, f3 = u.w;
                float f4 = w.x, f5 = w.y, f6 = w.z, f7 = w.w;
                float h0 = bf16_rt(f0), h1 = bf16_rt(f1), h2 = bf16_rt(f2), h3 = bf16_rt(f3);
                float h4 = bf16_rt(f4), h5 = bf16_rt(f5), h6 = bf16_rt(f6), h7 = bf16_rt(f7);
                uint4 hv, lv;
                hv.x = pack_bf16(h0, h1); hv.y = pack_bf16(h2, h3);
                hv.z = pack_bf16(h4, h5); hv.w = pack_bf16(h6, h7);
                lv.x = pack_bf16(f0 - h0, f1 - h1); lv.y = pack_bf16(f2 - h2, f3 - h3);
                lv.z = pack_bf16(f4 - h4, f5 - h5); lv.w = pack_bf16(f6 - h6, f7 - h7);
                int c8 = hf * 4 + jj;
                uint32_t off = (uint32_t)r8 * 128u + (uint32_t)((c8 ^ (r8 & 7)) * 16);
                *reinterpret_cast<uint4*>(smem + SM_A_HI + off) = hv;
                *reinterpret_cast<uint4*>(smem + SM_A_LO + off) = lv;
            }
        }
        {
            const uint4* src = reinterpret_cast<const uint4*>(g_wb + (size_t)ck * 49152);
            uint4* dst = reinterpret_cast<uint4*>(smem + SM_B_HI);
#pragma unroll
            for (int i = 0; i < 12; ++i) dst[tid + i * 256] = src[tid + i * 256];
        }
        __syncthreads();

#pragma unroll 1
        for (int kk = 0; kk < 4; ++kk) {
            uint32_t ah[2][4], al[2][4];
#pragma unroll
            for (int t16 = 0; t16 < 2; ++t16) {
                int row = a_row0 + t16 * 16;
                int c8  = kk * 2 + a_chi;
                uint32_t off = (uint32_t)row * 128u + (uint32_t)((c8 ^ (row & 7)) * 16);
                ldsm_x4(ah[t16], sb + SM_A_HI + off);
                ldsm_x4(al[t16], sb + SM_A_LO + off);
            }
            uint32_t bh[12][2], bl[12][2];
#pragma unroll
            for (int nt = 0; nt < 6; ++nt) {
                int k = kk * 16 + b_k0;
                int c = ((wn * 96 + nt * 16) >> 3) + (lane >> 4);
                int cs = (c & ~7) | ((c ^ k) & 7);
                uint32_t off = (uint32_t)k * 384u + (uint32_t)cs * 16u;
                uint32_t t[4];
                ldsm_x4_trans(t, sb + SM_B_HI + off);
                bh[2*nt][0] = t[0]; bh[2*nt][1] = t[1];
                bh[2*nt+1][0] = t[2]; bh[2*nt+1][1] = t[3];
                ldsm_x4_trans(t, sb + SM_B_LO + off);
                bl[2*nt][0] = t[0]; bl[2*nt][1] = t[1];
                bl[2*nt+1][0] = t[2]; bl[2*nt+1][1] = t[3];
            }
#pragma unroll
            for (int t16 = 0; t16 < 2; ++t16)
#pragma unroll
                for (int nt8 = 0; nt8 < 12; ++nt8) {
                    mma_bf16(acc[t16][nt8], ah[t16], bh[nt8]);
                    mma_bf16(acc[t16][nt8], ah[t16], bl[nt8]);
                    mma_bf16(acc[t16][nt8], al[t16], bh[nt8]);
                }
        }
        __syncthreads();
    }

#pragma unroll
    for (int t16 = 0; t16 < 2; ++t16) {
        int row0 = m0 + wm * 32 + t16 * 16 + (lane >> 2);
#pragma unroll
        for (int nt8 = 0; nt8 < 12; ++nt8) {
            int col = wn * 96 + nt8 * 8 + (lane & 3) * 2;
            int mat = col >> 6;
            int h   = col & 63;
            float* dst = (mat == 0) ? g_q : (mat == 1) ? g_k : g_v;
            *reinterpret_cast<float2*>(dst + (size_t)row0 * HH + h) =
                make_float2(acc[t16][nt8][0], acc[t16][nt8][1]);
            *reinterpret_cast<float2*>(dst + (size_t)(row0 + 8) * HH + h) =
                make_float2(acc[t16][nt8][2], acc[t16][nt8][3]);
        }
    }
}

// ---------------------------------------------------------------------------
// Tensor-core flash attention. One CTA = one batch, 8 warps, 32 q-rows each.
// K,V in SMEM as bf16 hi/lo ([key][64] rows, 128B, XOR-16B-chunk swizzle).
// QK: 2 passes (q_hi*k_hi + q_hi*k_lo). PV: 3 passes (ph*vh + ph*vl + pl*vh).
// ---------------------------------------------------------------------------
#define SM_K_HI  0
#define SM_K_LO  32768
#define SM_V_HI  65536
#define SM_V_LO  98304
#define SM_ATT   131072

__global__ __launch_bounds__(256) void attn_mma_kernel(float* __restrict__ out)
{
    extern __shared__ char smem[];
    const uint32_t sb = smem_u32(smem);
    const int b    = blockIdx.x;
    const int tid  = threadIdx.x;
    const int wid  = tid >> 5;
    const int lane = tid & 31;
    const size_t base = (size_t)b * TT * HH;

    // ---- stage K and V (fp32 -> bf16 hi/lo, swizzled) ----
    {
        const float4* kg = (const float4*)(g_k + base);
        const float4* vg = (const float4*)(g_v + base);
#pragma unroll
        for (int p = 0; p < 16; ++p) {
            int idx = tid + p * 256;            // 0..4095
            int key = idx >> 4;
            int j   = idx & 15;                 // float4 index within row
            uint32_t off = (uint32_t)key * 128u
                         + (uint32_t)((((j >> 1) ^ key) & 7) * 16)
                         + (uint32_t)((j & 1) * 8);
            float4 f = kg[idx];
            float hx = bf16_rt(f.x), hy = bf16_rt(f.y), hz = bf16_rt(f.z), hw = bf16_rt(f.w);
            *(uint2*)(smem + SM_K_HI + off) =
                make_uint2(pack_bf16(f.x, f.y), pack_bf16(f.z, f.w));
            *(uint2*)(smem + SM_K_LO + off) =
                make_uint2(pack_bf16(f.x - hx, f.y - hy), pack_bf16(f.z - hz, f.w - hw));
            f = vg[idx];
            hx = bf16_rt(f.x); hy = bf16_rt(f.y); hz = bf16_rt(f.z); hw = bf16_rt(f.w);
            *(uint2*)(smem + SM_V_HI + off) =
                make_uint2(pack_bf16(f.x, f.y), pack_bf16(f.z, f.w));
            *(uint2*)(smem + SM_V_LO + off) =
                make_uint2(pack_bf16(f.x - hx, f.y - hy), pack_bf16(f.z - hz, f.w - hw));
        }
    }
    __syncthreads();

    // SMSP-balanced triangle: chunks (0,7),(1,6),(2,5),(3,4) pair on SMSPs
    const int chunk = (wid < 4) ? wid : (11 - wid);
    const int q0    = chunk * 32;
    const float scale = 0.05103103630798287f;   // 384^-0.5 (embed dim C)

    // ---- Q A-fragments (hi only, scale folded) ----
    uint32_t qh[2][4][4];
#pragma unroll
    for (int i = 0; i < 2; ++i)
#pragma unroll
        for (int kt = 0; kt < 4; ++kt) {
            const float* qp = g_q + base
                + (size_t)(q0 + 16 * i + (lane >> 2)) * HH + kt * 16 + 2 * (lane & 3);
            float2 v0 = *(const float2*)qp;
            float2 v1 = *(const float2*)(qp + 8 * HH);
            float2 v2 = *(const float2*)(qp + 8);
            float2 v3 = *(const float2*)(qp + 8 * HH + 8);
            qh[i][kt][0] = pack_bf16(v0.x * scale, v0.y * scale);
            qh[i][kt][1] = pack_bf16(v1.x * scale, v1.y * scale);
            qh[i][kt][2] = pack_bf16(v2.x * scale, v2.y * scale);
            qh[i][kt][3] = pack_bf16(v3.x * scale, v3.y * scale);
        }

    float o[2][8][4];
#pragma unroll
    for (int i = 0; i < 2; ++i)
#pragma unroll
        for (int j = 0; j < 8; ++j)
#pragma unroll
            for (int r = 0; r < 4; ++r) o[i][j][r] = 0.0f;

    float mrow[2][2] = {{-INFINITY, -INFINITY}, {-INFINITY, -INFINITY}};
    float lrow[2][2] = {{0.0f, 0.0f}, {0.0f, 0.0f}};

    for (int kb = 0; kb <= chunk; ++kb) {
        // ---- S = Q K^T (scaled) ----
        float sc[2][4][4];
#pragma unroll
        for (int i = 0; i < 2; ++i)
#pragma unroll
            for (int j = 0; j < 4; ++j)
#pragma unroll
                for (int r = 0; r < 4; ++r) sc[i][j][r] = 0.0f;

#pragma unroll
        for (int kt = 0; kt < 4; ++kt) {
            uint32_t kbh[4][2], kbl[4][2];
#pragma unroll
            for (int jn = 0; jn < 4; ++jn) {
                int key = kb * 32 + jn * 8 + (lane >> 2);
                uint32_t rowb = (uint32_t)key * 128u + (uint32_t)(lane & 3) * 4u;
                uint32_t c0 = (uint32_t)(((kt * 2)     ^ (key & 7)) * 16);
                uint32_t c1 = (uint32_t)(((kt * 2 + 1) ^ (key & 7)) * 16);
                kbh[jn][0] = *(const uint32_t*)(smem + SM_K_HI + rowb + c0);
                kbh[jn][1] = *(const uint32_t*)(smem + SM_K_HI + rowb + c1);
                kbl[jn][0] = *(const uint32_t*)(smem + SM_K_LO + rowb + c0);
                kbl[jn][1] = *(const uint32_t*)(smem + SM_K_LO + rowb + c1);
            }
#pragma unroll
            for (int i = 0; i < 2; ++i)
#pragma unroll
                for (int jn = 0; jn < 4; ++jn) {
                    mma_bf16(sc[i][jn], qh[i][kt], kbh[jn]);
                    mma_bf16(sc[i][jn], qh[i][kt], kbl[jn]);
                }
        }

        // ---- causal mask on diagonal block ----
        if (kb == chunk) {
#pragma unroll
            for (int i = 0; i < 2; ++i) {
                int rl = 16 * i + (lane >> 2);
#pragma unroll
                for (int jn = 0; jn < 4; ++jn) {
                    int k0 = jn * 8 + 2 * (lane & 3);
                    if (k0     > rl    ) sc[i][jn][0] = -INFINITY;
                    if (k0 + 1 > rl    ) sc[i][jn][1] = -INFINITY;
                    if (k0     > rl + 8) sc[i][jn][2] = -INFINITY;
                    if (k0 + 1 > rl + 8) sc[i][jn][3] = -INFINITY;
                }
            }
        }

        // ---- online softmax + P pack ----
        uint32_t ph[2][2][4], pl[2][2][4];
#pragma unroll
        for (int i = 0; i < 2; ++i) {
            float mx0 = fmaxf(fmaxf(sc[i][0][0], sc[i][0][1]),
                              fmaxf(sc[i][1][0], sc[i][1][1]));
            mx0 = fmaxf(mx0, fmaxf(fmaxf(sc[i][2][0], sc[i][2][1]),
                                   fmaxf(sc[i][3][0], sc[i][3][1])));
            float mx1 = fmaxf(fmaxf(sc[i][0][2], sc[i][0][3]),
                              fmaxf(sc[i][1][2], sc[i][1][3]));
            mx1 = fmaxf(mx1, fmaxf(fmaxf(sc[i][2][2], sc[i][2][3]),
                                   fmaxf(sc[i][3][2], sc[i][3][3])));
            mx0 = fmaxf(mx0, __shfl_xor_sync(0xffffffffu, mx0, 1));
            mx0 = fmaxf(mx0, __shfl_xor_sync(0xffffffffu, mx0, 2));
            mx1 = fmaxf(mx1, __shfl_xor_sync(0xffffffffu, mx1, 1));
            mx1 = fmaxf(mx1, __shfl_xor_sync(0xffffffffu, mx1, 2));
            float nm0 = fmaxf(mrow[i][0], mx0);
            float nm1 = fmaxf(mrow[i][1], mx1);
            float cr0 = __expf(mrow[i][0] - nm0);
            float cr1 = __expf(mrow[i][1] - nm1);
            mrow[i][0] = nm0; mrow[i][1] = nm1;
            float rs0 = 0.0f, rs1 = 0.0f;
#pragma unroll
            for (int jn = 0; jn < 4; ++jn) {
                sc[i][jn][0] = __expf(sc[i][jn][0] - nm0); rs0 += sc[i][jn][0];
                sc[i][jn][1] = __expf(sc[i][jn][1] - nm0); rs0 += sc[i][jn][1];
                sc[i][jn][2] = __expf(sc[i][jn][2] - nm1); rs1 += sc[i][jn][2];
                sc[i][jn][3] = __expf(sc[i][jn][3] - nm1); rs1 += sc[i][jn][3];
            }
            rs0 += __shfl_xor_sync(0xffffffffu, rs0, 1);
            rs0 += __shfl_xor_sync(0xffffffffu, rs0, 2);
            rs1 += __shfl_xor_sync(0xffffffffu, rs1, 1);
            rs1 += __shfl_xor_sync(0xffffffffu, rs1, 2);
            lrow[i][0] = lrow[i][0] * cr0 + rs0;
            lrow[i][1] = lrow[i][1] * cr1 + rs1;
#pragma unroll
            for (int jd = 0; jd < 8; ++jd) {
                o[i][jd][0] *= cr0; o[i][jd][1] *= cr0;
                o[i][jd][2] *= cr1; o[i][jd][3] *= cr1;
            }
            // pack P accumulators straight into A-fragments (hi/lo split)
#pragma unroll
            for (int kp = 0; kp < 2; ++kp)
#pragma unroll
                for (int rr = 0; rr < 4; ++rr) {
                    int jt = 2 * kp + (rr >> 1);
                    int e  = (rr & 1) * 2;
                    float p0 = sc[i][jt][e], p1 = sc[i][jt][e + 1];
                    float h0 = bf16_rt(p0), h1 = bf16_rt(p1);
                    ph[i][kp][rr] = pack_bf16(p0, p1);
                    pl[i][kp][rr] = pack_bf16(p0 - h0, p1 - h1);
                }
        }

        // ---- O += P V ----
#pragma unroll
        for (int kp = 0; kp < 2; ++kp) {
            int keyr = kb * 32 + kp * 16 + (lane & 15);
#pragma unroll
            for (int g = 0; g < 4; ++g) {
                uint32_t cidx = (uint32_t)(((2 * g + (lane >> 4)) ^ keyr) & 7);
                uint32_t addr = sb + SM_V_HI + (uint32_t)keyr * 128u + cidx * 16u;
                uint32_t th[4], tl[4];
                ldsm_x4_trans(th, addr);
                ldsm_x4_trans(tl, addr + (SM_V_LO - SM_V_HI));
                uint32_t bh0[2] = {th[0], th[1]}, bh1[2] = {th[2], th[3]};
                uint32_t bl0[2] = {tl[0], tl[1]}, bl1[2] = {tl[2], tl[3]};
#pragma unroll
                for (int i = 0; i < 2; ++i) {
                    mma_bf16(o[i][2*g],     ph[i][kp], bh0);
                    mma_bf16(o[i][2*g],     ph[i][kp], bl0);
                    mma_bf16(o[i][2*g],     pl[i][kp], bh0);
                    mma_bf16(o[i][2*g+1],   ph[i][kp], bh1);
                    mma_bf16(o[i][2*g+1],   ph[i][kp], bl1);
                    mma_bf16(o[i][2*g+1],   pl[i][kp], bh1);
                }
            }
        }
    }

    // ---- epilogue: normalize and store ----
#pragma unroll
    for (int i = 0; i < 2; ++i) {
        float inv0 = 1.0f / lrow[i][0];
        float inv1 = 1.0f / lrow[i][1];
        int row = q0 + 16 * i + (lane >> 2);
        float* op = out + base + (size_t)row * HH + 2 * (lane & 3);
#pragma unroll
        for (int jd = 0; jd < 8; ++jd) {
            *(float2*)(op + jd * 8) =
                make_float2(o[i][jd][0] * inv0, o[i][jd][1] * inv0);
            *(float2*)(op + 8 * HH + jd * 8) =
                make_float2(o[i][jd][2] * inv1, o[i][jd][3] * inv1);
        }
    }
}

// ---------------------------------------------------------------------------
extern "C" void kernel_launch(void* const* d_in, const int* in_sizes, int n_in,
                              void* d_out, int out_size)
{
    (void)in_sizes; (void)n_in; (void)out_size;
    const float* x  = (const float*)d_in[0];
    const float* Wk = (const float*)d_in[1];
    const float* Wq = (const float*)d_in[2];
    const float* Wv = (const float*)d_in[3];
    float* out = (float*)d_out;

    setup_wb_kernel<<<(6 * 64 * 192 + 255) / 256, 256>>>(Wk, Wq, Wv);

    cudaFuncSetAttribute(qkv_mma_kernel, cudaFuncAttributeMaxDynamicSharedMemorySize,
                         SM_TOTAL);
    qkv_mma_kernel<<<(BB * TT) / 128, 256, SM_TOTAL>>>(x);

    cudaFuncSetAttribute(attn_mma_kernel, cudaFuncAttributeMaxDynamicSharedMemorySize,
                         SM_ATT);
    attn_mma_kernel<<<BB, 256, SM_ATT>>>(out);
}

// round 15
// speedup vs baseline: 1.8362x; 1.1540x over previous
#include <cuda_runtime.h>
#include <cuda_bf16.h>
#include <math.h>
#include <stdint.h>

#define BB 1024
#define TT 256
#define CC 384
#define HH 64

// ---------------------------------------------------------------------------
// Device scratch (no allocations allowed)
// q: [b][row][32] u32 (bf16 pairs, softmax scale folded, hi only)
// k/v: per-batch pre-swizzled SMEM images, hi and lo (8192 u32 per batch each)
// ---------------------------------------------------------------------------
__device__ uint32_t g_qh[BB * TT * HH / 2];
__device__ uint32_t g_kh[BB * TT * HH / 2];
__device__ uint32_t g_kl[BB * TT * HH / 2];
__device__ uint32_t g_vh[BB * TT * HH / 2];
__device__ uint32_t g_vl[BB * TT * HH / 2];
// Pre-swizzled SMEM image of W^T bf16 hi/lo per 64-wide K chunk
__device__ unsigned char g_wb[6 * 2 * 24576];

// ---------------------------------------------------------------------------
// helpers
// ---------------------------------------------------------------------------
__device__ __forceinline__ uint32_t smem_u32(const void* p) {
    uint32_t a;
    asm("{ .reg .u64 t; cvta.to.shared.u64 t, %1; cvt.u32.u64 %0, t; }"
        : "=r"(a) : "l"(p));
    return a;
}

__device__ __forceinline__ void ldsm_x4(uint32_t r[4], uint32_t addr) {
    asm volatile("ldmatrix.sync.aligned.m8n8.x4.shared.b16 {%0,%1,%2,%3}, [%4];"
                 : "=r"(r[0]), "=r"(r[1]), "=r"(r[2]), "=r"(r[3]) : "r"(addr));
}

__device__ __forceinline__ void ldsm_x4_trans(uint32_t r[4], uint32_t addr) {
    asm volatile("ldmatrix.sync.aligned.m8n8.x4.trans.shared.b16 {%0,%1,%2,%3}, [%4];"
                 : "=r"(r[0]), "=r"(r[1]), "=r"(r[2]), "=r"(r[3]) : "r"(addr));
}

__device__ __forceinline__ void mma_bf16(float c[4], const uint32_t a[4],
                                         const uint32_t b[2]) {
    asm volatile(
        "mma.sync.aligned.m16n8k16.row.col.f32.bf16.bf16.f32 "
        "{%0,%1,%2,%3}, {%4,%5,%6,%7}, {%8,%9}, {%0,%1,%2,%3};"
        : "+f"(c[0]), "+f"(c[1]), "+f"(c[2]), "+f"(c[3])
        : "r"(a[0]), "r"(a[1]), "r"(a[2]), "r"(a[3]), "r"(b[0]), "r"(b[1]));
}

__device__ __forceinline__ uint32_t pack_bf16(float a, float b) {
    __nv_bfloat162 t = __floats2bfloat162_rn(a, b);
    return *reinterpret_cast<uint32_t*>(&t);
}

__device__ __forceinline__ float bf16_rt(float a) {
    return __bfloat162float(__float2bfloat16(a));
}

__device__ __forceinline__ void cp_async16(uint32_t dst, const void* src) {
    asm volatile("cp.async.cg.shared.global [%0], [%1], 16;"
                 :: "r"(dst), "l"(src) : "memory");
}
#define CP_COMMIT() asm volatile("cp.async.commit_group;" ::: "memory")
#define CP_WAIT0()  asm volatile("cp.async.wait_group 0;" ::: "memory")

#define SCALE 0.05103103630798287f   // 384^-0.5 (embed dim C)

// ---------------------------------------------------------------------------
// Setup: pre-swizzled W^T bf16 hi/lo image (unchanged)
// ---------------------------------------------------------------------------
__global__ void setup_wb_kernel(const float* __restrict__ Wk,
                                const float* __restrict__ Wq,
                                const float* __restrict__ Wv)
{
    int idx = blockIdx.x * 256 + threadIdx.x;
    if (idx >= 6 * 64 * 192) return;
    int ck  = idx / (64 * 192);
    int rem = idx % (64 * 192);
    int k   = rem / 192;
    int n   = rem % 192;
    int mat = n >> 6, h = n & 63;
    const float* W = (mat == 0) ? Wq : (mat == 1) ? Wk : Wv;
    float v = W[(size_t)(ck * 64 + k) * HH + h];
    __nv_bfloat16 hi = __float2bfloat16(v);
    __nv_bfloat16 lo = __float2bfloat16(v - __bfloat162float(hi));
    int c  = n >> 3;
    int cs = (c & ~7) | ((c ^ k) & 7);
    uint32_t off = (uint32_t)k * 384u + (uint32_t)cs * 16u + (uint32_t)(n & 7) * 2u;
    unsigned char* base = g_wb + (size_t)ck * 49152;
    *reinterpret_cast<__nv_bfloat16*>(base + off)         = hi;
    *reinterpret_cast<__nv_bfloat16*>(base + 24576 + off) = lo;
}

// ---------------------------------------------------------------------------
// QKV projection via mma.sync bf16 split, double-buffered smem + cp.async B.
// CTA: M=128, N=192, K=384 in 6 chunks of 64. 256 threads (8 warps 4m x 2n).
// Epilogue writes bf16 outputs: q (scale folded, hi), k/v (hi+lo, swizzled).
// ---------------------------------------------------------------------------
#define SM_A_HI  0
#define SM_A_LO  16384
#define SM_B_HI  32768
#define SM_BUF   81920
#define SM_TOTAL 163840

__global__ __launch_bounds__(256) void qkv_mma_kernel(const float* __restrict__ x)
{
    extern __shared__ char smem[];
    const uint32_t sb = smem_u32(smem);
    const int tid  = threadIdx.x;
    const int wid  = tid >> 5;
    const int lane = tid & 31;
    const int m0   = blockIdx.x * 128;
    const int wm   = wid & 3;
    const int wn   = wid >> 2;

    float acc[2][12][4];
#pragma unroll
    for (int i = 0; i < 2; ++i)
#pragma unroll
        for (int j = 0; j < 12; ++j)
#pragma unroll
            for (int r = 0; r < 4; ++r) acc[i][j][r] = 0.0f;

    // x staging assignment: row r8 = tid>>1, 32-col half hf
    const int r8 = tid >> 1;
    const int hf = tid & 1;
    const float* xrow = x + (size_t)(m0 + r8) * CC + hf * 32;

    const int a_row0 = wm * 32 + (lane & 15);
    const int a_chi  = lane >> 4;
    const int b_k0   = lane & 15;

    // staging helpers -------------------------------------------------------
    float4 xs[8];
    // A swizzled store offset for this thread (c8 = hf*4 + jj)
    auto stage_x = [&](int bufb) {
#pragma unroll
        for (int jj = 0; jj < 4; ++jj) {
            float4 u = xs[2 * jj];
            float4 w = xs[2 * jj + 1];
            float f0 = u.x, f1 = u.y, f2 = u.z, f3 = u.w;
            float f4 = w.x, f5 = w.y, f6 = w.z, f7 = w.w;
            float h0 = bf16_rt(f0), h1 = bf16_rt(f1), h2 = bf16_rt(f2), h3 = bf16_rt(f3);
            float h4 = bf16_rt(f4), h5 = bf16_rt(f5), h6 = bf16_rt(f6), h7 = bf16_rt(f7);
            uint4 hv, lv;
            hv.x = pack_bf16(h0, h1); hv.y = pack_bf16(h2, h3);
            hv.z = pack_bf16(h4, h5); hv.w = pack_bf16(h6, h7);
            lv.x = pack_bf16(f0 - h0, f1 - h1); lv.y = pack_bf16(f2 - h2, f3 - h3);
            lv.z = pack_bf16(f4 - h4, f5 - h5); lv.w = pack_bf16(f6 - h6, f7 - h7);
            int c8 = hf * 4 + jj;
            uint32_t off = (uint32_t)r8 * 128u + (uint32_t)((c8 ^ (r8 & 7)) * 16);
            *reinterpret_cast<uint4*>(smem + bufb + SM_A_HI + off) = hv;
            *reinterpret_cast<uint4*>(smem + bufb + SM_A_LO + off) = lv;
        }
    };
    auto copy_b = [&](int bufb, int ck) {
        const char* src = (const char*)g_wb + (size_t)ck * 49152 + tid * 16;
        uint32_t dst = sb + bufb + SM_B_HI + tid * 16;
#pragma unroll
        for (int i = 0; i < 12; ++i)
            cp_async16(dst + i * 4096, src + i * 4096);
    };

    // prologue: stage chunk 0, prefetch chunk 1 into regs
#pragma unroll
    for (int i = 0; i < 8; ++i) xs[i] = ((const float4*)xrow)[i];
    stage_x(0);
    copy_b(0, 0);
    CP_COMMIT();
#pragma unroll
    for (int i = 0; i < 8; ++i) xs[i] = ((const float4*)(xrow + 64))[i];
    CP_WAIT0();
    __syncthreads();

    for (int ck = 0; ck < 6; ++ck) {
        const int bufb  = (ck & 1) * SM_BUF;
        const int nbufb = ((ck + 1) & 1) * SM_BUF;
        // stage next chunk (x from regs, B via cp.async)
        if (ck < 5) {
            stage_x(nbufb);
            copy_b(nbufb, ck + 1);
            CP_COMMIT();
            if (ck < 4) {
                const float4* p = (const float4*)(xrow + (ck + 2) * 64);
#pragma unroll
                for (int i = 0; i < 8; ++i) xs[i] = p[i];
            }
        }

        // compute on current buffer
        const uint32_t sab = sb + bufb;
#pragma unroll 1
        for (int kk = 0; kk < 4; ++kk) {
            uint32_t ah[2][4], al[2][4];
#pragma unroll
            for (int t16 = 0; t16 < 2; ++t16) {
                int row = a_row0 + t16 * 16;
                int c8  = kk * 2 + a_chi;
                uint32_t off = (uint32_t)row * 128u + (uint32_t)((c8 ^ (row & 7)) * 16);
                ldsm_x4(ah[t16], sab + SM_A_HI + off);
                ldsm_x4(al[t16], sab + SM_A_LO + off);
            }
#pragma unroll
            for (int nt = 0; nt < 6; ++nt) {
                int k = kk * 16 + b_k0;
                int c = ((wn * 96 + nt * 16) >> 3) + (lane >> 4);
                int cs = (c & ~7) | ((c ^ k) & 7);
                uint32_t off = (uint32_t)k * 384u + (uint32_t)cs * 16u;
                uint32_t th[4], tl[4];
                ldsm_x4_trans(th, sab + SM_B_HI + off);
                ldsm_x4_trans(tl, sab + SM_B_HI + 24576 + off);
                uint32_t b0h[2] = {th[0], th[1]}, b1h[2] = {th[2], th[3]};
                uint32_t b0l[2] = {tl[0], tl[1]}, b1l[2] = {tl[2], tl[3]};
#pragma unroll
                for (int t16 = 0; t16 < 2; ++t16) {
                    mma_bf16(acc[t16][2*nt],   ah[t16], b0h);
                    mma_bf16(acc[t16][2*nt],   ah[t16], b0l);
                    mma_bf16(acc[t16][2*nt],   al[t16], b0h);
                    mma_bf16(acc[t16][2*nt+1], ah[t16], b1h);
                    mma_bf16(acc[t16][2*nt+1], ah[t16], b1l);
                    mma_bf16(acc[t16][2*nt+1], al[t16], b1h);
                }
            }
        }
        if (ck < 5) CP_WAIT0();
        __syncthreads();
    }

    // --- epilogue: write bf16 outputs ---
    const int batch = m0 >> 8;
    uint32_t* qb  = g_qh + (size_t)batch * 8192;
    uint32_t* khb = g_kh + (size_t)batch * 8192;
    uint32_t* klb = g_kl + (size_t)batch * 8192;
    uint32_t* vhb = g_vh + (size_t)batch * 8192;
    uint32_t* vlb = g_vl + (size_t)batch * 8192;

#pragma unroll
    for (int t16 = 0; t16 < 2; ++t16) {
        int row0 = m0 + wm * 32 + t16 * 16 + (lane >> 2);
        int key0 = row0 & 255;
#pragma unroll
        for (int nt8 = 0; nt8 < 12; ++nt8) {
            int col = wn * 96 + nt8 * 8 + (lane & 3) * 2;
            int mat = col >> 6;
            int c   = col & 63;
            float a0 = acc[t16][nt8][0], a1 = acc[t16][nt8][1];
            float a2 = acc[t16][nt8][2], a3 = acc[t16][nt8][3];
            if (mat == 0) {
                qb[(key0)     * 32 + (c >> 1)] = pack_bf16(a0 * SCALE, a1 * SCALE);
                qb[(key0 + 8) * 32 + (c >> 1)] = pack_bf16(a2 * SCALE, a3 * SCALE);
            } else {
                uint32_t* hb = (mat == 1) ? khb : vhb;
                uint32_t* lb = (mat == 1) ? klb : vlb;
                int j = c >> 3;                       // 16B chunk index
                int w4 = (c & 7) >> 1;                // u32 within chunk
                uint32_t i0 = (uint32_t)key0 * 32 + (uint32_t)(((j ^ (key0 & 7)) << 2) + w4);
                int key1 = key0 + 8;
                uint32_t i1 = (uint32_t)key1 * 32 + (uint32_t)(((j ^ (key1 & 7)) << 2) + w4);
                float h0 = bf16_rt(a0), h1 = bf16_rt(a1);
                float h2 = bf16_rt(a2), h3 = bf16_rt(a3);
                hb[i0] = pack_bf16(a0, a1);
                lb[i0] = pack_bf16(a0 - h0, a1 - h1);
                hb[i1] = pack_bf16(a2, a3);
                lb[i1] = pack_bf16(a2 - h2, a3 - h3);
            }
        }
    }
}

// ---------------------------------------------------------------------------
// Tensor-core flash attention. One CTA = one batch, 8 warps, 32 q-rows each.
// K,V smem images are pure cp.async copies of pre-swizzled global images.
// QK: 2 passes. PV: 3 passes.
// ---------------------------------------------------------------------------
#define SM_K_HI  0
#define SM_K_LO  32768
#define SM_V_HI  65536
#define SM_V_LO  98304
#define SM_ATT   131072

__global__ __launch_bounds__(256) void attn_mma_kernel(float* __restrict__ out)
{
    extern __shared__ char smem[];
    const uint32_t sb = smem_u32(smem);
    const int b    = blockIdx.x;
    const int tid  = threadIdx.x;
    const int wid  = tid >> 5;
    const int lane = tid & 31;
    const size_t base  = (size_t)b * TT * HH;
    const size_t base2 = (size_t)b * 8192;        // u32 units

    // ---- stage K and V images (pure async copy, 128 KB) ----
    {
        uint32_t dst = sb + tid * 16;
        const char* skh = (const char*)(g_kh + base2) + tid * 16;
        const char* skl = (const char*)(g_kl + base2) + tid * 16;
        const char* svh = (const char*)(g_vh + base2) + tid * 16;
        const char* svl = (const char*)(g_vl + base2) + tid * 16;
#pragma unroll
        for (int i = 0; i < 8; ++i) {
            cp_async16(dst + SM_K_HI + i * 4096, skh + i * 4096);
            cp_async16(dst + SM_K_LO + i * 4096, skl + i * 4096);
            cp_async16(dst + SM_V_HI + i * 4096, svh + i * 4096);
            cp_async16(dst + SM_V_LO + i * 4096, svl + i * 4096);
        }
        CP_COMMIT();
    }

    // SMSP-balanced triangle: chunks (0,7),(1,6),(2,5),(3,4) pair on SMSPs
    const int chunk = (wid < 4) ? wid : (11 - wid);
    const int q0    = chunk * 32;

    // ---- Q A-fragments (pre-scaled bf16 hi from proj) ----
    uint32_t qh[2][4][4];
    {
        const uint32_t* qb = g_qh + base2;
#pragma unroll
        for (int i = 0; i < 2; ++i) {
            int row = q0 + 16 * i + (lane >> 2);
#pragma unroll
            for (int kt = 0; kt < 4; ++kt) {
                int idx = row * 32 + kt * 8 + (lane & 3);
                qh[i][kt][0] = qb[idx];
                qh[i][kt][1] = qb[idx + 256];
                qh[i][kt][2] = qb[idx + 4];
                qh[i][kt][3] = qb[idx + 260];
            }
        }
    }

    float o[2][8][4];
#pragma unroll
    for (int i = 0; i < 2; ++i)
#pragma unroll
        for (int j = 0; j < 8; ++j)
#pragma unroll
            for (int r = 0; r < 4; ++r) o[i][j][r] = 0.0f;

    float mrow[2][2] = {{-INFINITY, -INFINITY}, {-INFINITY, -INFINITY}};
    float lrow[2][2] = {{0.0f, 0.0f}, {0.0f, 0.0f}};

    CP_WAIT0();
    __syncthreads();

    for (int kb = 0; kb <= chunk; ++kb) {
        // ---- S = Q K^T ----
        float sc[2][4][4];
#pragma unroll
        for (int i = 0; i < 2; ++i)
#pragma unroll
            for (int j = 0; j < 4; ++j)
#pragma unroll
                for (int r = 0; r < 4; ++r) sc[i][j][r] = 0.0f;

#pragma unroll
        for (int kt = 0; kt < 4; ++kt) {
            uint32_t kbh[4][2], kbl[4][2];
#pragma unroll
            for (int jn = 0; jn < 4; ++jn) {
                int key = kb * 32 + jn * 8 + (lane >> 2);
                uint32_t rowb = (uint32_t)key * 128u + (uint32_t)(lane & 3) * 4u;
                uint32_t c0 = (uint32_t)(((kt * 2)     ^ (key & 7)) * 16);
                uint32_t c1 = (uint32_t)(((kt * 2 + 1) ^ (key & 7)) * 16);
                kbh[jn][0] = *(const uint32_t*)(smem + SM_K_HI + rowb + c0);
                kbh[jn][1] = *(const uint32_t*)(smem + SM_K_HI + rowb + c1);
                kbl[jn][0] = *(const uint32_t*)(smem + SM_K_LO + rowb + c0);
                kbl[jn][1] = *(const uint32_t*)(smem + SM_K_LO + rowb + c1);
            }
#pragma unroll
            for (int i = 0; i < 2; ++i)
#pragma unroll
                for (int jn = 0; jn < 4; ++jn) {
                    mma_bf16(sc[i][jn], qh[i][kt], kbh[jn]);
                    mma_bf16(sc[i][jn], qh[i][kt], kbl[jn]);
                }
        }

        // ---- causal mask on diagonal block ----
        if (kb == chunk) {
#pragma unroll
            for (int i = 0; i < 2; ++i) {
                int rl = 16 * i + (lane >> 2);
#pragma unroll
                for (int jn = 0; jn < 4; ++jn) {
                    int k0 = jn * 8 + 2 * (lane & 3);
                    if (k0     > rl    ) sc[i][jn][0] = -INFINITY;
                    if (k0 + 1 > rl    ) sc[i][jn][1] = -INFINITY;
                    if (k0     > rl + 8) sc[i][jn][2] = -INFINITY;
                    if (k0 + 1 > rl + 8) sc[i][jn][3] = -INFINITY;
                }
            }
        }

        // ---- online softmax + P pack ----
        uint32_t ph[2][2][4], pl[2][2][4];
#pragma unroll
        for (int i = 0; i < 2; ++i) {
            float mx0 = fmaxf(fmaxf(sc[i][0][0], sc[i][0][1]),
                              fmaxf(sc[i][1][0], sc[i][1][1]));
            mx0 = fmaxf(mx0, fmaxf(fmaxf(sc[i][2][0], sc[i][2][1]),
                                   fmaxf(sc[i][3][0], sc[i][3][1])));
            float mx1 = fmaxf(fmaxf(sc[i][0][2], sc[i][0][3]),
                              fmaxf(sc[i][1][2], sc[i][1][3]));
            mx1 = fmaxf(mx1, fmaxf(fmaxf(sc[i][2][2], sc[i][2][3]),
                                   fmaxf(sc[i][3][2], sc[i][3][3])));
            mx0 = fmaxf(mx0, __shfl_xor_sync(0xffffffffu, mx0, 1));
            mx0 = fmaxf(mx0, __shfl_xor_sync(0xffffffffu, mx0, 2));
            mx1 = fmaxf(mx1, __shfl_xor_sync(0xffffffffu, mx1, 1));
            mx1 = fmaxf(mx1, __shfl_xor_sync(0xffffffffu, mx1, 2));
            float nm0 = fmaxf(mrow[i][0], mx0);
            float nm1 = fmaxf(mrow[i][1], mx1);
            float cr0 = __expf(mrow[i][0] - nm0);
            float cr1 = __expf(mrow[i][1] - nm1);
            mrow[i][0] = nm0; mrow[i][1] = nm1;
            float rs0 = 0.0f, rs1 = 0.0f;
#pragma unroll
            for (int jn = 0; jn < 4; ++jn) {
                sc[i][jn][0] = __expf(sc[i][jn][0] - nm0); rs0 += sc[i][jn][0];
                sc[i][jn][1] = __expf(sc[i][jn][1] - nm0); rs0 += sc[i][jn][1];
                sc[i][jn][2] = __expf(sc[i][jn][2] - nm1); rs1 += sc[i][jn][2];
                sc[i][jn][3] = __expf(sc[i][jn][3] - nm1); rs1 += sc[i][jn][3];
            }
            rs0 += __shfl_xor_sync(0xffffffffu, rs0, 1);
            rs0 += __shfl_xor_sync(0xffffffffu, rs0, 2);
            rs1 += __shfl_xor_sync(0xffffffffu, rs1, 1);
            rs1 += __shfl_xor_sync(0xffffffffu, rs1, 2);
            lrow[i][0] = lrow[i][0] * cr0 + rs0;
            lrow[i][1] = lrow[i][1] * cr1 + rs1;
#pragma unroll
            for (int jd = 0; jd < 8; ++jd) {
                o[i][jd][0] *= cr0; o[i][jd][1] *= cr0;
                o[i][jd][2] *= cr1; o[i][jd][3] *= cr1;
            }
#pragma unroll
            for (int kp = 0; kp < 2; ++kp)
#pragma unroll
                for (int rr = 0; rr < 4; ++rr) {
                    int jt = 2 * kp + (rr >> 1);
                    int e  = (rr & 1) * 2;
                    float p0 = sc[i][jt][e], p1 = sc[i][jt][e + 1];
                    float h0 = bf16_rt(p0), h1 = bf16_rt(p1);
                    ph[i][kp][rr] = pack_bf16(p0, p1);
                    pl[i][kp][rr] = pack_bf16(p0 - h0, p1 - h1);
                }
        }

        // ---- O += P V ----
#pragma unroll
        for (int kp = 0; kp < 2; ++kp) {
            int keyr = kb * 32 + kp * 16 + (lane & 15);
#pragma unroll
            for (int g = 0; g < 4; ++g) {
                uint32_t cidx = (uint32_t)(((2 * g + (lane >> 4)) ^ keyr) & 7);
                uint32_t addr = sb + SM_V_HI + (uint32_t)keyr * 128u + cidx * 16u;
                uint32_t th[4], tl[4];
                ldsm_x4_trans(th, addr);
                ldsm_x4_trans(tl, addr + (SM_V_LO - SM_V_HI));
                uint32_t bh0[2] = {th[0], th[1]}, bh1[2] = {th[2], th[3]};
                uint32_t bl0[2] = {tl[0], tl[1]}, bl1[2] = {tl[2], tl[3]};
#pragma unroll
                for (int i = 0; i < 2; ++i) {
                    mma_bf16(o[i][2*g],   ph[i][kp], bh0);
                    mma_bf16(o[i][2*g],   ph[i][kp], bl0);
                    mma_bf16(o[i][2*g],   pl[i][kp], bh0);
                    mma_bf16(o[i][2*g+1], ph[i][kp], bh1);
                    mma_bf16(o[i][2*g+1], ph[i][kp], bl1);
                    mma_bf16(o[i][2*g+1], pl[i][kp], bh1);
                }
            }
        }
    }

    // ---- epilogue: normalize and store ----
#pragma unroll
    for (int i = 0; i < 2; ++i) {
        float inv0 = 1.0f / lrow[i][0];
        float inv1 = 1.0f / lrow[i][1];
        int row = q0 + 16 * i + (lane >> 2);
        float* op = out + base + (size_t)row * HH + 2 * (lane & 3);
#pragma unroll
        for (int jd = 0; jd < 8; ++jd) {
            *(float2*)(op + jd * 8) =
                make_float2(o[i][jd][0] * inv0, o[i][jd][1] * inv0);
            *(float2*)(op + 8 * HH + jd * 8) =
                make_float2(o[i][jd][2] * inv1, o[i][jd][3] * inv1);
        }
    }
}

// ---------------------------------------------------------------------------
extern "C" void kernel_launch(void* const* d_in, const int* in_sizes, int n_in,
                              void* d_out, int out_size)
{
    (void)in_sizes; (void)n_in; (void)out_size;
    const float* x  = (const float*)d_in[0];
    const float* Wk = (const float*)d_in[1];
    const float* Wq = (const float*)d_in[2];
    const float* Wv = (const float*)d_in[3];
    float* out = (float*)d_out;

    setup_wb_kernel<<<(6 * 64 * 192 + 255) / 256, 256>>>(Wk, Wq, Wv);

    cudaFuncSetAttribute(qkv_mma_kernel, cudaFuncAttributeMaxDynamicSharedMemorySize,
                         SM_TOTAL);
    qkv_mma_kernel<<<(BB * TT) / 128, 256, SM_TOTAL>>>(x);

    cudaFuncSetAttribute(attn_mma_kernel, cudaFuncAttributeMaxDynamicSharedMemorySize,
                         SM_ATT);
    attn_mma_kernel<<<BB, 256, SM_ATT>>>(out);
}

// round 16
// speedup vs baseline: 2.2028x; 1.1997x over previous
#include <cuda_runtime.h>
#include <cuda_bf16.h>
#include <math.h>
#include <stdint.h>

#define BB 1024
#define TT 256
#define CC 384
#define HH 64

// ---------------------------------------------------------------------------
// Device scratch (no allocations allowed)
// q: [b][row][32] u32 (bf16 pairs, softmax scale folded, hi only)
// k/v: per-batch pre-swizzled SMEM images, hi and lo (8192 u32 per batch each)
// ---------------------------------------------------------------------------
__device__ uint32_t g_qh[BB * TT * HH / 2];
__device__ uint32_t g_kh[BB * TT * HH / 2];
__device__ uint32_t g_kl[BB * TT * HH / 2];
__device__ uint32_t g_vh[BB * TT * HH / 2];
__device__ uint32_t g_vl[BB * TT * HH / 2];
// Pre-swizzled tf32 W^T image: [6 chunks][192 n][64 k] (16B-chunk swizzled)
__device__ uint32_t g_wt[6 * 192 * 64];

// ---------------------------------------------------------------------------
// helpers
// ---------------------------------------------------------------------------
__device__ __forceinline__ uint32_t smem_u32(const void* p) {
    uint32_t a;
    asm("{ .reg .u64 t; cvta.to.shared.u64 t, %1; cvt.u32.u64 %0, t; }"
        : "=r"(a) : "l"(p));
    return a;
}

__device__ __forceinline__ void ldsm_x4(uint32_t r[4], uint32_t addr) {
    asm volatile("ldmatrix.sync.aligned.m8n8.x4.shared.b16 {%0,%1,%2,%3}, [%4];"
                 : "=r"(r[0]), "=r"(r[1]), "=r"(r[2]), "=r"(r[3]) : "r"(addr));
}

__device__ __forceinline__ void ldsm_x4_trans(uint32_t r[4], uint32_t addr) {
    asm volatile("ldmatrix.sync.aligned.m8n8.x4.trans.shared.b16 {%0,%1,%2,%3}, [%4];"
                 : "=r"(r[0]), "=r"(r[1]), "=r"(r[2]), "=r"(r[3]) : "r"(addr));
}

__device__ __forceinline__ void mma_bf16(float c[4], const uint32_t a[4],
                                         const uint32_t b[2]) {
    asm volatile(
        "mma.sync.aligned.m16n8k16.row.col.f32.bf16.bf16.f32 "
        "{%0,%1,%2,%3}, {%4,%5,%6,%7}, {%8,%9}, {%0,%1,%2,%3};"
        : "+f"(c[0]), "+f"(c[1]), "+f"(c[2]), "+f"(c[3])
        : "r"(a[0]), "r"(a[1]), "r"(a[2]), "r"(a[3]), "r"(b[0]), "r"(b[1]));
}

__device__ __forceinline__ void mma_tf32(float c[4], const uint32_t a[4],
                                         const uint32_t b[2]) {
    asm volatile(
        "mma.sync.aligned.m16n8k8.row.col.f32.tf32.tf32.f32 "
        "{%0,%1,%2,%3}, {%4,%5,%6,%7}, {%8,%9}, {%0,%1,%2,%3};"
        : "+f"(c[0]), "+f"(c[1]), "+f"(c[2]), "+f"(c[3])
        : "r"(a[0]), "r"(a[1]), "r"(a[2]), "r"(a[3]), "r"(b[0]), "r"(b[1]));
}

__device__ __forceinline__ uint32_t pack_bf16(float a, float b) {
    __nv_bfloat162 t = __floats2bfloat162_rn(a, b);
    return *reinterpret_cast<uint32_t*>(&t);
}

__device__ __forceinline__ float bf16_rt(float a) {
    return __bfloat162float(__float2bfloat16(a));
}

__device__ __forceinline__ void cp_async16(uint32_t dst, const void* src) {
    asm volatile("cp.async.cg.shared.global [%0], [%1], 16;"
                 :: "r"(dst), "l"(src) : "memory");
}
#define CP_COMMIT() asm volatile("cp.async.commit_group;" ::: "memory")
#define CP_WAIT0()  asm volatile("cp.async.wait_group 0;" ::: "memory")
#define CP_WAIT1()  asm volatile("cp.async.wait_group 1;" ::: "memory")

#define SCALE 0.05103103630798287f   // 384^-0.5 (embed dim C)

// 16B-chunk swizzle for 256B rows: keep bit3, XOR low 3 bits with row&7
__device__ __forceinline__ int sw16(int c, int r) {
    return (c & 8) | ((c ^ (r & 7)) & 7);
}

// ---------------------------------------------------------------------------
// Setup: pre-swizzled tf32 W^T image. [ck][n][k]: n = mat*64+h (q|k|v).
// ---------------------------------------------------------------------------
__global__ void setup_wt_kernel(const float* __restrict__ Wk,
                                const float* __restrict__ Wq,
                                const float* __restrict__ Wv)
{
    int idx = blockIdx.x * 256 + threadIdx.x;    // 6*64*192 = 73728
    if (idx >= 6 * 64 * 192) return;
    int ck  = idx / (64 * 192);
    int rem = idx % (64 * 192);
    int k   = rem / 192;
    int n   = rem % 192;
    int mat = n >> 6, h = n & 63;
    const float* W = (mat == 0) ? Wq : (mat == 1) ? Wk : Wv;
    float v = W[(size_t)(ck * 64 + k) * HH + h];
    uint32_t t;
    asm("cvt.rna.tf32.f32 %0, %1;" : "=r"(t) : "f"(v));
    int cs = sw16(k >> 2, n);
    g_wt[(size_t)ck * 12288 + (size_t)n * 64 + cs * 4 + (k & 3)] = t;
}

// ---------------------------------------------------------------------------
// QKV projection via single-pass tf32 mma, double-buffered cp.async pipeline.
// CTA: M=128, N=192, K=384 in 6 chunks of 64. 256 threads (8 warps, 4m x 2n).
// A tile: x fp32 direct (raw bits as tf32). B tile: pre-rounded tf32 image.
// Epilogue (unchanged): q bf16-hi scale-folded; k/v bf16 hi/lo images.
// ---------------------------------------------------------------------------
#define PSM_A    0
#define PSM_B    32768
#define PSM_BUF  81920
#define PSM_TOTAL 163840

__global__ __launch_bounds__(256) void qkv_mma_kernel(const float* __restrict__ x)
{
    extern __shared__ char smem[];
    const uint32_t sb = smem_u32(smem);
    const int tid  = threadIdx.x;
    const int wid  = tid >> 5;
    const int lane = tid & 31;
    const int m0   = blockIdx.x * 128;
    const int wm   = wid & 3;
    const int wn   = wid >> 2;

    float acc[2][12][4];
#pragma unroll
    for (int i = 0; i < 2; ++i)
#pragma unroll
        for (int j = 0; j < 12; ++j)
#pragma unroll
            for (int r = 0; r < 4; ++r) acc[i][j][r] = 0.0f;

    // ldmatrix address components
    const int a_row  = wm * 32 + (lane & 15);          // + t16*16
    const int a_chi  = lane >> 4;                      // k-chunk select
    const int b_nrow = wn * 96 + ((lane >> 4) << 3) + (lane & 7);  // + ng*16
    const int b_chi  = (lane >> 3) & 1;

    // staging: A = 8 cp.async16 (x direct), B = 12 cp.async16 (linear image)
    const char* xbase = (const char*)x + (size_t)m0 * 1536;
    const int st_row = tid >> 1;                       // two threads per row
    const int st_c0  = (tid & 1) * 8;                  // 8 chunks each

    for (int pre = 0; pre < 1; ++pre) {                // prologue: stage chunk 0
#pragma unroll
        for (int t = 0; t < 8; ++t) {
            int c = st_c0 + t;
            cp_async16(sb + PSM_A + st_row * 256 + sw16(c, st_row) * 16,
                       xbase + (size_t)st_row * 1536 + c * 16);
        }
        const char* wb = (const char*)g_wt + tid * 16;
        uint32_t dstb = sb + PSM_B + tid * 16;
#pragma unroll
        for (int i = 0; i < 12; ++i)
            cp_async16(dstb + i * 4096, wb + i * 4096);
        CP_COMMIT();
    }

    for (int ck = 0; ck < 6; ++ck) {
        const uint32_t buf = (uint32_t)(ck & 1) * PSM_BUF;
        if (ck < 5) {
            // stage next chunk into other buffer
            const uint32_t nb = (uint32_t)((ck + 1) & 1) * PSM_BUF;
            const char* xsrc = xbase + (size_t)(ck + 1) * 256;
#pragma unroll
            for (int t = 0; t < 8; ++t) {
                int c = st_c0 + t;
                cp_async16(sb + nb + PSM_A + st_row * 256 + sw16(c, st_row) * 16,
                           xsrc + (size_t)st_row * 1536 + c * 16);
            }
            const char* wb = (const char*)g_wt + (size_t)(ck + 1) * 49152 + tid * 16;
            uint32_t dstb = sb + nb + PSM_B + tid * 16;
#pragma unroll
            for (int i = 0; i < 12; ++i)
                cp_async16(dstb + i * 4096, wb + i * 4096);
            CP_COMMIT();
            CP_WAIT1();          // current chunk's group done; next still flying
        } else {
            CP_WAIT0();
        }
        __syncthreads();

        const uint32_t sa  = sb + buf + PSM_A;
        const uint32_t sbb = sb + buf + PSM_B;
#pragma unroll 1
        for (int ks = 0; ks < 8; ++ks) {
            uint32_t ah[2][4];
#pragma unroll
            for (int t16 = 0; t16 < 2; ++t16) {
                int row = a_row + t16 * 16;
                int c   = ks * 2 + a_chi;
                ldsm_x4(ah[t16], sa + (uint32_t)row * 256u + (uint32_t)sw16(c, row) * 16u);
            }
#pragma unroll
            for (int ng = 0; ng < 6; ++ng) {
                int nrow = b_nrow + ng * 16;
                int c    = ks * 2 + b_chi;
                uint32_t bt[4];
                ldsm_x4(bt, sbb + (uint32_t)nrow * 256u + (uint32_t)sw16(c, nrow) * 16u);
                uint32_t b0[2] = {bt[0], bt[1]};
                uint32_t b1[2] = {bt[2], bt[3]};
#pragma unroll
                for (int t16 = 0; t16 < 2; ++t16) {
                    mma_tf32(acc[t16][2 * ng],     ah[t16], b0);
                    mma_tf32(acc[t16][2 * ng + 1], ah[t16], b1);
                }
            }
        }
        __syncthreads();
    }

    // --- epilogue: write bf16 outputs (unchanged interface) ---
    const int batch = m0 >> 8;
    uint32_t* qb  = g_qh + (size_t)batch * 8192;
    uint32_t* khb = g_kh + (size_t)batch * 8192;
    uint32_t* klb = g_kl + (size_t)batch * 8192;
    uint32_t* vhb = g_vh + (size_t)batch * 8192;
    uint32_t* vlb = g_vl + (size_t)batch * 8192;

#pragma unroll
    for (int t16 = 0; t16 < 2; ++t16) {
        int row0 = m0 + wm * 32 + t16 * 16 + (lane >> 2);
        int key0 = row0 & 255;
#pragma unroll
        for (int nt8 = 0; nt8 < 12; ++nt8) {
            int col = wn * 96 + nt8 * 8 + (lane & 3) * 2;
            int mat = col >> 6;
            int c   = col & 63;
            float a0 = acc[t16][nt8][0], a1 = acc[t16][nt8][1];
            float a2 = acc[t16][nt8][2], a3 = acc[t16][nt8][3];
            if (mat == 0) {
                qb[(key0)     * 32 + (c >> 1)] = pack_bf16(a0 * SCALE, a1 * SCALE);
                qb[(key0 + 8) * 32 + (c >> 1)] = pack_bf16(a2 * SCALE, a3 * SCALE);
            } else {
                uint32_t* hb = (mat == 1) ? khb : vhb;
                uint32_t* lb = (mat == 1) ? klb : vlb;
                int j = c >> 3;
                int w4 = (c & 7) >> 1;
                uint32_t i0 = (uint32_t)key0 * 32 + (uint32_t)(((j ^ (key0 & 7)) << 2) + w4);
                int key1 = key0 + 8;
                uint32_t i1 = (uint32_t)key1 * 32 + (uint32_t)(((j ^ (key1 & 7)) << 2) + w4);
                float h0 = bf16_rt(a0), h1 = bf16_rt(a1);
                float h2 = bf16_rt(a2), h3 = bf16_rt(a3);
                hb[i0] = pack_bf16(a0, a1);
                lb[i0] = pack_bf16(a0 - h0, a1 - h1);
                hb[i1] = pack_bf16(a2, a3);
                lb[i1] = pack_bf16(a2 - h2, a3 - h3);
            }
        }
    }
}

// ---------------------------------------------------------------------------
// Tensor-core flash attention (unchanged from R5 — passing at 2.06e-4).
// ---------------------------------------------------------------------------
#define SM_K_HI  0
#define SM_K_LO  32768
#define SM_V_HI  65536
#define SM_V_LO  98304
#define SM_ATT   131072

__global__ __launch_bounds__(256) void attn_mma_kernel(float* __restrict__ out)
{
    extern __shared__ char smem[];
    const uint32_t sb = smem_u32(smem);
    const int b    = blockIdx.x;
    const int tid  = threadIdx.x;
    const int wid  = tid >> 5;
    const int lane = tid & 31;
    const size_t base  = (size_t)b * TT * HH;
    const size_t base2 = (size_t)b * 8192;

    {
        uint32_t dst = sb + tid * 16;
        const char* skh = (const char*)(g_kh + base2) + tid * 16;
        const char* skl = (const char*)(g_kl + base2) + tid * 16;
        const char* svh = (const char*)(g_vh + base2) + tid * 16;
        const char* svl = (const char*)(g_vl + base2) + tid * 16;
#pragma unroll
        for (int i = 0; i < 8; ++i) {
            cp_async16(dst + SM_K_HI + i * 4096, skh + i * 4096);
            cp_async16(dst + SM_K_LO + i * 4096, skl + i * 4096);
            cp_async16(dst + SM_V_HI + i * 4096, svh + i * 4096);
            cp_async16(dst + SM_V_LO + i * 4096, svl + i * 4096);
        }
        CP_COMMIT();
    }

    const int chunk = (wid < 4) ? wid : (11 - wid);
    const int q0    = chunk * 32;

    uint32_t qh[2][4][4];
    {
        const uint32_t* qb = g_qh + base2;
#pragma unroll
        for (int i = 0; i < 2; ++i) {
            int row = q0 + 16 * i + (lane >> 2);
#pragma unroll
            for (int kt = 0; kt < 4; ++kt) {
                int idx = row * 32 + kt * 8 + (lane & 3);
                qh[i][kt][0] = qb[idx];
                qh[i][kt][1] = qb[idx + 256];
                qh[i][kt][2] = qb[idx + 4];
                qh[i][kt][3] = qb[idx + 260];
            }
        }
    }

    float o[2][8][4];
#pragma unroll
    for (int i = 0; i < 2; ++i)
#pragma unroll
        for (int j = 0; j < 8; ++j)
#pragma unroll
            for (int r = 0; r < 4; ++r) o[i][j][r] = 0.0f;

    float mrow[2][2] = {{-INFINITY, -INFINITY}, {-INFINITY, -INFINITY}};
    float lrow[2][2] = {{0.0f, 0.0f}, {0.0f, 0.0f}};

    CP_WAIT0();
    __syncthreads();

    for (int kb = 0; kb <= chunk; ++kb) {
        float sc[2][4][4];
#pragma unroll
        for (int i = 0; i < 2; ++i)
#pragma unroll
            for (int j = 0; j < 4; ++j)
#pragma unroll
                for (int r = 0; r < 4; ++r) sc[i][j][r] = 0.0f;

#pragma unroll
        for (int kt = 0; kt < 4; ++kt) {
            uint32_t kbh[4][2], kbl[4][2];
#pragma unroll
            for (int jn = 0; jn < 4; ++jn) {
                int key = kb * 32 + jn * 8 + (lane >> 2);
                uint32_t rowb = (uint32_t)key * 128u + (uint32_t)(lane & 3) * 4u;
                uint32_t c0 = (uint32_t)(((kt * 2)     ^ (key & 7)) * 16);
                uint32_t c1 = (uint32_t)(((kt * 2 + 1) ^ (key & 7)) * 16);
                kbh[jn][0] = *(const uint32_t*)(smem + SM_K_HI + rowb + c0);
                kbh[jn][1] = *(const uint32_t*)(smem + SM_K_HI + rowb + c1);
                kbl[jn][0] = *(const uint32_t*)(smem + SM_K_LO + rowb + c0);
                kbl[jn][1] = *(const uint32_t*)(smem + SM_K_LO + rowb + c1);
            }
#pragma unroll
            for (int i = 0; i < 2; ++i)
#pragma unroll
                for (int jn = 0; jn < 4; ++jn) {
                    mma_bf16(sc[i][jn], qh[i][kt], kbh[jn]);
                    mma_bf16(sc[i][jn], qh[i][kt], kbl[jn]);
                }
        }

        if (kb == chunk) {
#pragma unroll
            for (int i = 0; i < 2; ++i) {
                int rl = 16 * i + (lane >> 2);
#pragma unroll
                for (int jn = 0; jn < 4; ++jn) {
                    int k0 = jn * 8 + 2 * (lane & 3);
                    if (k0     > rl    ) sc[i][jn][0] = -INFINITY;
                    if (k0 + 1 > rl    ) sc[i][jn][1] = -INFINITY;
                    if (k0     > rl + 8) sc[i][jn][2] = -INFINITY;
                    if (k0 + 1 > rl + 8) sc[i][jn][3] = -INFINITY;
                }
            }
        }

        uint32_t ph[2][2][4], pl[2][2][4];
#pragma unroll
        for (int i = 0; i < 2; ++i) {
            float mx0 = fmaxf(fmaxf(sc[i][0][0], sc[i][0][1]),
                              fmaxf(sc[i][1][0], sc[i][1][1]));
            mx0 = fmaxf(mx0, fmaxf(fmaxf(sc[i][2][0], sc[i][2][1]),
                                   fmaxf(sc[i][3][0], sc[i][3][1])));
            float mx1 = fmaxf(fmaxf(sc[i][0][2], sc[i][0][3]),
                              fmaxf(sc[i][1][2], sc[i][1][3]));
            mx1 = fmaxf(mx1, fmaxf(fmaxf(sc[i][2][2], sc[i][2][3]),
                                   fmaxf(sc[i][3][2], sc[i][3][3])));
            mx0 = fmaxf(mx0, __shfl_xor_sync(0xffffffffu, mx0, 1));
            mx0 = fmaxf(mx0, __shfl_xor_sync(0xffffffffu, mx0, 2));
            mx1 = fmaxf(mx1, __shfl_xor_sync(0xffffffffu, mx1, 1));
            mx1 = fmaxf(mx1, __shfl_xor_sync(0xffffffffu, mx1, 2));
            float nm0 = fmaxf(mrow[i][0], mx0);
            float nm1 = fmaxf(mrow[i][1], mx1);
            float cr0 = __expf(mrow[i][0] - nm0);
            float cr1 = __expf(mrow[i][1] - nm1);
            mrow[i][0] = nm0; mrow[i][1] = nm1;
            float rs0 = 0.0f, rs1 = 0.0f;
#pragma unroll
            for (int jn = 0; jn < 4; ++jn) {
                sc[i][jn][0] = __expf(sc[i][jn][0] - nm0); rs0 += sc[i][jn][0];
                sc[i][jn][1] = __expf(sc[i][jn][1] - nm0); rs0 += sc[i][jn][1];
                sc[i][jn][2] = __expf(sc[i][jn][2] - nm1); rs1 += sc[i][jn][2];
                sc[i][jn][3] = __expf(sc[i][jn][3] - nm1); rs1 += sc[i][jn][3];
            }
            rs0 += __shfl_xor_sync(0xffffffffu, rs0, 1);
            rs0 += __shfl_xor_sync(0xffffffffu, rs0, 2);
            rs1 += __shfl_xor_sync(0xffffffffu, rs1, 1);
            rs1 += __shfl_xor_sync(0xffffffffu, rs1, 2);
            lrow[i][0] = lrow[i][0] * cr0 + rs0;
            lrow[i][1] = lrow[i][1] * cr1 + rs1;
#pragma unroll
            for (int jd = 0; jd < 8; ++jd) {
                o[i][jd][0] *= cr0; o[i][jd][1] *= cr0;
                o[i][jd][2] *= cr1; o[i][jd][3] *= cr1;
            }
#pragma unroll
            for (int kp = 0; kp < 2; ++kp)
#pragma unroll
                for (int rr = 0; rr < 4; ++rr) {
                    int jt = 2 * kp + (rr >> 1);
                    int e  = (rr & 1) * 2;
                    float p0 = sc[i][jt][e], p1 = sc[i][jt][e + 1];
                    float h0 = bf16_rt(p0), h1 = bf16_rt(p1);
                    ph[i][kp][rr] = pack_bf16(p0, p1);
                    pl[i][kp][rr] = pack_bf16(p0 - h0, p1 - h1);
                }
        }

#pragma unroll
        for (int kp = 0; kp < 2; ++kp) {
            int keyr = kb * 32 + kp * 16 + (lane & 15);
#pragma unroll
            for (int g = 0; g < 4; ++g) {
                uint32_t cidx = (uint32_t)(((2 * g + (lane >> 4)) ^ keyr) & 7);
                uint32_t addr = sb + SM_V_HI + (uint32_t)keyr * 128u + cidx * 16u;
                uint32_t th[4], tl[4];
                ldsm_x4_trans(th, addr);
                ldsm_x4_trans(tl, addr + (SM_V_LO - SM_V_HI));
                uint32_t bh0[2] = {th[0], th[1]}, bh1[2] = {th[2], th[3]};
                uint32_t bl0[2] = {tl[0], tl[1]}, bl1[2] = {tl[2], tl[3]};
#pragma unroll
                for (int i = 0; i < 2; ++i) {
                    mma_bf16(o[i][2*g],   ph[i][kp], bh0);
                    mma_bf16(o[i][2*g],   ph[i][kp], bl0);
                    mma_bf16(o[i][2*g],   pl[i][kp], bh0);
                    mma_bf16(o[i][2*g+1], ph[i][kp], bh1);
                    mma_bf16(o[i][2*g+1], ph[i][kp], bl1);
                    mma_bf16(o[i][2*g+1], pl[i][kp], bh1);
                }
            }
        }
    }

#pragma unroll
    for (int i = 0; i < 2; ++i) {
        float inv0 = 1.0f / lrow[i][0];
        float inv1 = 1.0f / lrow[i][1];
        int row = q0 + 16 * i + (lane >> 2);
        float* op = out + base + (size_t)row * HH + 2 * (lane & 3);
#pragma unroll
        for (int jd = 0; jd < 8; ++jd) {
            *(float2*)(op + jd * 8) =
                make_float2(o[i][jd][0] * inv0, o[i][jd][1] * inv0);
            *(float2*)(op + 8 * HH + jd * 8) =
                make_float2(o[i][jd][2] * inv1, o[i][jd][3] * inv1);
        }
    }
}

// ---------------------------------------------------------------------------
extern "C" void kernel_launch(void* const* d_in, const int* in_sizes, int n_in,
                              void* d_out, int out_size)
{
    (void)in_sizes; (void)n_in; (void)out_size;
    const float* x  = (const float*)d_in[0];
    const float* Wk = (const float*)d_in[1];
    const float* Wq = (const float*)d_in[2];
    const float* Wv = (const float*)d_in[3];
    float* out = (float*)d_out;

    setup_wt_kernel<<<(6 * 64 * 192 + 255) / 256, 256>>>(Wk, Wq, Wv);

    cudaFuncSetAttribute(qkv_mma_kernel, cudaFuncAttributeMaxDynamicSharedMemorySize,
                         PSM_TOTAL);
    qkv_mma_kernel<<<(BB * TT) / 128, 256, PSM_TOTAL>>>(x);

    cudaFuncSetAttribute(attn_mma_kernel, cudaFuncAttributeMaxDynamicSharedMemorySize,
                         SM_ATT);
    attn_mma_kernel<<<BB, 256, SM_ATT>>>(out);
}

// round 17
// speedup vs baseline: 2.9665x; 1.3467x over previous
#include <cuda_runtime.h>
#include <cuda_fp16.h>
#include <math.h>
#include <stdint.h>

#define BB 1024
#define TT 256
#define CC 384
#define HH 64

// ---------------------------------------------------------------------------
// Device scratch (no allocations allowed)
// q: fp16 scale-folded [b][row][32 u32]
// k: fp16 single, per-batch swizzled image; v: fp16 hi/lo swizzled images
// ---------------------------------------------------------------------------
__device__ uint32_t g_q16[BB * 8192];
__device__ uint32_t g_k16[BB * 8192];
__device__ uint32_t g_vh16[BB * 8192];
__device__ uint32_t g_vl16[BB * 8192];
// Pre-swizzled fp16 W^T image per 64-wide K chunk: [k 0..63][192 n], 24576 B
__device__ unsigned char g_w16[6 * 24576];

// ---------------------------------------------------------------------------
// helpers
// ---------------------------------------------------------------------------
__device__ __forceinline__ uint32_t smem_u32(const void* p) {
    uint32_t a;
    asm("{ .reg .u64 t; cvta.to.shared.u64 t, %1; cvt.u32.u64 %0, t; }"
        : "=r"(a) : "l"(p));
    return a;
}

__device__ __forceinline__ void ldsm_x4(uint32_t r[4], uint32_t addr) {
    asm volatile("ldmatrix.sync.aligned.m8n8.x4.shared.b16 {%0,%1,%2,%3}, [%4];"
                 : "=r"(r[0]), "=r"(r[1]), "=r"(r[2]), "=r"(r[3]) : "r"(addr));
}

__device__ __forceinline__ void ldsm_x4_trans(uint32_t r[4], uint32_t addr) {
    asm volatile("ldmatrix.sync.aligned.m8n8.x4.trans.shared.b16 {%0,%1,%2,%3}, [%4];"
                 : "=r"(r[0]), "=r"(r[1]), "=r"(r[2]), "=r"(r[3]) : "r"(addr));
}

__device__ __forceinline__ void mma_f16(float c[4], const uint32_t a[4],
                                        const uint32_t b[2]) {
    asm volatile(
        "mma.sync.aligned.m16n8k16.row.col.f32.f16.f16.f32 "
        "{%0,%1,%2,%3}, {%4,%5,%6,%7}, {%8,%9}, {%0,%1,%2,%3};"
        : "+f"(c[0]), "+f"(c[1]), "+f"(c[2]), "+f"(c[3])
        : "r"(a[0]), "r"(a[1]), "r"(a[2]), "r"(a[3]), "r"(b[0]), "r"(b[1]));
}

__device__ __forceinline__ uint32_t packh(float a, float b) {
    __half2 t = __floats2half2_rn(a, b);
    return *reinterpret_cast<uint32_t*>(&t);
}

__device__ __forceinline__ float h16_rt(float a) {   // round-trip through fp16
    return __half2float(__float2half_rn(a));
}

__device__ __forceinline__ void cp_async16(uint32_t dst, const void* src) {
    asm volatile("cp.async.cg.shared.global [%0], [%1], 16;"
                 :: "r"(dst), "l"(src) : "memory");
}
#define CP_COMMIT() asm volatile("cp.async.commit_group;" ::: "memory")
#define CP_WAIT0()  asm volatile("cp.async.wait_group 0;" ::: "memory")

#define SCALE 0.05103103630798287f   // 384^-0.5 (embed dim C)

// ---------------------------------------------------------------------------
// Setup: pre-swizzled fp16 W^T image. [ck][k][n]: n = mat*64+h (q|k|v).
// ---------------------------------------------------------------------------
__global__ void setup_w16_kernel(const float* __restrict__ Wk,
                                 const float* __restrict__ Wq,
                                 const float* __restrict__ Wv)
{
    int idx = blockIdx.x * 256 + threadIdx.x;    // 6*64*192 = 73728
    if (idx >= 6 * 64 * 192) return;
    int ck  = idx / (64 * 192);
    int rem = idx % (64 * 192);
    int k   = rem / 192;
    int n   = rem % 192;
    int mat = n >> 6, h = n & 63;
    const float* W = (mat == 0) ? Wq : (mat == 1) ? Wk : Wv;
    float v = W[(size_t)(ck * 64 + k) * HH + h];
    int c  = n >> 3;
    int cs = (c & ~7) | ((c ^ k) & 7);
    uint32_t off = (uint32_t)k * 384u + (uint32_t)cs * 16u + (uint32_t)(n & 7) * 2u;
    __half hv = __float2half_rn(v);
    *reinterpret_cast<__half*>(g_w16 + (size_t)ck * 24576 + off) = hv;
}

// ---------------------------------------------------------------------------
// QKV projection: single-pass fp16 mma, double-buffered (A via reg-convert,
// B via cp.async). CTA: M=128, N=192, K=384 in 6 chunks of 64.
// 256 threads, 8 warps (4m x 2n), warp tile 32m x 96n.
// ---------------------------------------------------------------------------
#define PSM_A    0
#define PSM_B    16384
#define PSM_BUF  40960
#define PSM_TOTAL 81920

__global__ __launch_bounds__(256) void qkv_mma_kernel(const float* __restrict__ x)
{
    extern __shared__ char smem[];
    const uint32_t sb = smem_u32(smem);
    const int tid  = threadIdx.x;
    const int wid  = tid >> 5;
    const int lane = tid & 31;
    const int m0   = blockIdx.x * 128;
    const int wm   = wid & 3;
    const int wn   = wid >> 2;

    float acc[2][12][4];
#pragma unroll
    for (int i = 0; i < 2; ++i)
#pragma unroll
        for (int j = 0; j < 12; ++j)
#pragma unroll
            for (int r = 0; r < 4; ++r) acc[i][j][r] = 0.0f;

    // x staging: thread owns row r8, 32-col half hf
    const int r8 = tid >> 1;
    const int hf = tid & 1;
    const float* xrow = x + (size_t)(m0 + r8) * CC + hf * 32;

    const int a_row0 = wm * 32 + (lane & 15);
    const int a_chi  = lane >> 4;
    const int b_k0   = lane & 15;

    float4 xs[8];
    auto stage_x = [&](int bufb) {
#pragma unroll
        for (int jj = 0; jj < 4; ++jj) {
            float4 u = xs[2 * jj];
            float4 w = xs[2 * jj + 1];
            uint4 hv;
            hv.x = packh(u.x, u.y); hv.y = packh(u.z, u.w);
            hv.z = packh(w.x, w.y); hv.w = packh(w.z, w.w);
            int c8 = hf * 4 + jj;
            uint32_t off = (uint32_t)r8 * 128u + (uint32_t)((c8 ^ (r8 & 7)) * 16);
            *reinterpret_cast<uint4*>(smem + bufb + PSM_A + off) = hv;
        }
    };
    auto copy_b = [&](int bufb, int ck) {
        const char* src = (const char*)g_w16 + (size_t)ck * 24576 + tid * 16;
        uint32_t dst = sb + bufb + PSM_B + tid * 16;
#pragma unroll
        for (int i = 0; i < 6; ++i)
            cp_async16(dst + i * 4096, src + i * 4096);
    };

    // prologue: stage chunk 0, prefetch chunk 1 into regs
#pragma unroll
    for (int i = 0; i < 8; ++i) xs[i] = ((const float4*)xrow)[i];
    stage_x(0);
    copy_b(0, 0);
    CP_COMMIT();
#pragma unroll
    for (int i = 0; i < 8; ++i) xs[i] = ((const float4*)(xrow + 64))[i];
    CP_WAIT0();
    __syncthreads();

    for (int ck = 0; ck < 6; ++ck) {
        const int bufb  = (ck & 1) * PSM_BUF;
        const int nbufb = ((ck + 1) & 1) * PSM_BUF;
        if (ck < 5) {
            stage_x(nbufb);
            copy_b(nbufb, ck + 1);
            CP_COMMIT();
            if (ck < 4) {
                const float4* p = (const float4*)(xrow + (ck + 2) * 64);
#pragma unroll
                for (int i = 0; i < 8; ++i) xs[i] = p[i];
            }
        }

        const uint32_t sab = sb + bufb;
#pragma unroll 1
        for (int kk = 0; kk < 4; ++kk) {
            uint32_t ah[2][4];
#pragma unroll
            for (int t16 = 0; t16 < 2; ++t16) {
                int row = a_row0 + t16 * 16;
                int c8  = kk * 2 + a_chi;
                uint32_t off = (uint32_t)row * 128u + (uint32_t)((c8 ^ (row & 7)) * 16);
                ldsm_x4(ah[t16], sab + PSM_A + off);
            }
#pragma unroll
            for (int nt = 0; nt < 6; ++nt) {
                int k = kk * 16 + b_k0;
                int c = ((wn * 96 + nt * 16) >> 3) + (lane >> 4);
                int cs = (c & ~7) | ((c ^ k) & 7);
                uint32_t off = (uint32_t)k * 384u + (uint32_t)cs * 16u;
                uint32_t t[4];
                ldsm_x4_trans(t, sab + PSM_B + off);
                uint32_t b0[2] = {t[0], t[1]};
                uint32_t b1[2] = {t[2], t[3]};
#pragma unroll
                for (int t16 = 0; t16 < 2; ++t16) {
                    mma_f16(acc[t16][2*nt],   ah[t16], b0);
                    mma_f16(acc[t16][2*nt+1], ah[t16], b1);
                }
            }
        }
        if (ck < 5) CP_WAIT0();
        __syncthreads();
    }

    // --- epilogue: write fp16 outputs ---
    const int batch = m0 >> 8;
    uint32_t* qb  = g_q16  + (size_t)batch * 8192;
    uint32_t* kb_ = g_k16  + (size_t)batch * 8192;
    uint32_t* vhb = g_vh16 + (size_t)batch * 8192;
    uint32_t* vlb = g_vl16 + (size_t)batch * 8192;

#pragma unroll
    for (int t16 = 0; t16 < 2; ++t16) {
        int row0 = m0 + wm * 32 + t16 * 16 + (lane >> 2);
        int key0 = row0 & 255;
#pragma unroll
        for (int nt8 = 0; nt8 < 12; ++nt8) {
            int col = wn * 96 + nt8 * 8 + (lane & 3) * 2;
            int mat = col >> 6;
            int c   = col & 63;
            float a0 = acc[t16][nt8][0], a1 = acc[t16][nt8][1];
            float a2 = acc[t16][nt8][2], a3 = acc[t16][nt8][3];
            if (mat == 0) {
                qb[(key0)     * 32 + (c >> 1)] = packh(a0 * SCALE, a1 * SCALE);
                qb[(key0 + 8) * 32 + (c >> 1)] = packh(a2 * SCALE, a3 * SCALE);
            } else {
                int j = c >> 3;
                int w4 = (c & 7) >> 1;
                uint32_t i0 = (uint32_t)key0 * 32 + (uint32_t)(((j ^ (key0 & 7)) << 2) + w4);
                int key1 = key0 + 8;
                uint32_t i1 = (uint32_t)key1 * 32 + (uint32_t)(((j ^ (key1 & 7)) << 2) + w4);
                if (mat == 1) {
                    kb_[i0] = packh(a0, a1);
                    kb_[i1] = packh(a2, a3);
                } else {
                    float h0 = h16_rt(a0), h1 = h16_rt(a1);
                    float h2 = h16_rt(a2), h3 = h16_rt(a3);
                    vhb[i0] = packh(a0, a1);
                    vlb[i0] = packh(a0 - h0, a1 - h1);
                    vhb[i1] = packh(a2, a3);
                    vlb[i1] = packh(a2 - h2, a3 - h3);
                }
            }
        }
    }
}

// ---------------------------------------------------------------------------
// Tensor-core flash attention, fp16. One CTA = one batch, 8 warps.
// QK: single pass (q,k fp16). PV: 2 passes (p fp16 single, v fp16 hi/lo).
// ---------------------------------------------------------------------------
#define SM_K   0
#define SM_VH  32768
#define SM_VL  65536
#define SM_ATT 98304

__global__ __launch_bounds__(256) void attn_mma_kernel(float* __restrict__ out)
{
    extern __shared__ char smem[];
    const uint32_t sb = smem_u32(smem);
    const int b    = blockIdx.x;
    const int tid  = threadIdx.x;
    const int wid  = tid >> 5;
    const int lane = tid & 31;
    const size_t base  = (size_t)b * TT * HH;
    const size_t base2 = (size_t)b * 8192;

    // ---- stage K, VH, VL images (pure async copy, 96 KB) ----
    {
        uint32_t dst = sb + tid * 16;
        const char* sk  = (const char*)(g_k16  + base2) + tid * 16;
        const char* svh = (const char*)(g_vh16 + base2) + tid * 16;
        const char* svl = (const char*)(g_vl16 + base2) + tid * 16;
#pragma unroll
        for (int i = 0; i < 8; ++i) {
            cp_async16(dst + SM_K  + i * 4096, sk  + i * 4096);
            cp_async16(dst + SM_VH + i * 4096, svh + i * 4096);
            cp_async16(dst + SM_VL + i * 4096, svl + i * 4096);
        }
        CP_COMMIT();
    }

    // SMSP-balanced triangle: chunks (0,7),(1,6),(2,5),(3,4) pair on SMSPs
    const int chunk = (wid < 4) ? wid : (11 - wid);
    const int q0    = chunk * 32;

    // ---- Q A-fragments (pre-scaled fp16 from proj) ----
    uint32_t qh[2][4][4];
    {
        const uint32_t* qb = g_q16 + base2;
#pragma unroll
        for (int i = 0; i < 2; ++i) {
            int row = q0 + 16 * i + (lane >> 2);
#pragma unroll
            for (int kt = 0; kt < 4; ++kt) {
                int idx = row * 32 + kt * 8 + (lane & 3);
                qh[i][kt][0] = qb[idx];
                qh[i][kt][1] = qb[idx + 256];
                qh[i][kt][2] = qb[idx + 4];
                qh[i][kt][3] = qb[idx + 260];
            }
        }
    }

    float o[2][8][4];
#pragma unroll
    for (int i = 0; i < 2; ++i)
#pragma unroll
        for (int j = 0; j < 8; ++j)
#pragma unroll
            for (int r = 0; r < 4; ++r) o[i][j][r] = 0.0f;

    float mrow[2][2] = {{-INFINITY, -INFINITY}, {-INFINITY, -INFINITY}};
    float lrow[2][2] = {{0.0f, 0.0f}, {0.0f, 0.0f}};

    CP_WAIT0();
    __syncthreads();

    for (int kb = 0; kb <= chunk; ++kb) {
        // ---- S = Q K^T (single fp16 pass) ----
        float sc[2][4][4];
#pragma unroll
        for (int i = 0; i < 2; ++i)
#pragma unroll
            for (int j = 0; j < 4; ++j)
#pragma unroll
                for (int r = 0; r < 4; ++r) sc[i][j][r] = 0.0f;

#pragma unroll
        for (int kt = 0; kt < 4; ++kt) {
            uint32_t kbf[4][2];
#pragma unroll
            for (int jn = 0; jn < 4; ++jn) {
                int key = kb * 32 + jn * 8 + (lane >> 2);
                uint32_t rowb = (uint32_t)key * 128u + (uint32_t)(lane & 3) * 4u;
                uint32_t c0 = (uint32_t)(((kt * 2)     ^ (key & 7)) * 16);
                uint32_t c1 = (uint32_t)(((kt * 2 + 1) ^ (key & 7)) * 16);
                kbf[jn][0] = *(const uint32_t*)(smem + SM_K + rowb + c0);
                kbf[jn][1] = *(const uint32_t*)(smem + SM_K + rowb + c1);
            }
#pragma unroll
            for (int i = 0; i < 2; ++i)
#pragma unroll
                for (int jn = 0; jn < 4; ++jn)
                    mma_f16(sc[i][jn], qh[i][kt], kbf[jn]);
        }

        // ---- causal mask on diagonal block ----
        if (kb == chunk) {
#pragma unroll
            for (int i = 0; i < 2; ++i) {
                int rl = 16 * i + (lane >> 2);
#pragma unroll
                for (int jn = 0; jn < 4; ++jn) {
                    int k0 = jn * 8 + 2 * (lane & 3);
                    if (k0     > rl    ) sc[i][jn][0] = -INFINITY;
                    if (k0 + 1 > rl    ) sc[i][jn][1] = -INFINITY;
                    if (k0     > rl + 8) sc[i][jn][2] = -INFINITY;
                    if (k0 + 1 > rl + 8) sc[i][jn][3] = -INFINITY;
                }
            }
        }

        // ---- online softmax + P pack (fp16 single) ----
        uint32_t ph[2][2][4];
#pragma unroll
        for (int i = 0; i < 2; ++i) {
            float mx0 = fmaxf(fmaxf(sc[i][0][0], sc[i][0][1]),
                              fmaxf(sc[i][1][0], sc[i][1][1]));
            mx0 = fmaxf(mx0, fmaxf(fmaxf(sc[i][2][0], sc[i][2][1]),
                                   fmaxf(sc[i][3][0], sc[i][3][1])));
            float mx1 = fmaxf(fmaxf(sc[i][0][2], sc[i][0][3]),
                              fmaxf(sc[i][1][2], sc[i][1][3]));
            mx1 = fmaxf(mx1, fmaxf(fmaxf(sc[i][2][2], sc[i][2][3]),
                                   fmaxf(sc[i][3][2], sc[i][3][3])));
            mx0 = fmaxf(mx0, __shfl_xor_sync(0xffffffffu, mx0, 1));
            mx0 = fmaxf(mx0, __shfl_xor_sync(0xffffffffu, mx0, 2));
            mx1 = fmaxf(mx1, __shfl_xor_sync(0xffffffffu, mx1, 1));
            mx1 = fmaxf(mx1, __shfl_xor_sync(0xffffffffu, mx1, 2));
            float nm0 = fmaxf(mrow[i][0], mx0);
            float nm1 = fmaxf(mrow[i][1], mx1);
            float cr0 = __expf(mrow[i][0] - nm0);
            float cr1 = __expf(mrow[i][1] - nm1);
            mrow[i][0] = nm0; mrow[i][1] = nm1;
            float rs0 = 0.0f, rs1 = 0.0f;
#pragma unroll
            for (int jn = 0; jn < 4; ++jn) {
                sc[i][jn][0] = __expf(sc[i][jn][0] - nm0); rs0 += sc[i][jn][0];
                sc[i][jn][1] = __expf(sc[i][jn][1] - nm0); rs0 += sc[i][jn][1];
                sc[i][jn][2] = __expf(sc[i][jn][2] - nm1); rs1 += sc[i][jn][2];
                sc[i][jn][3] = __expf(sc[i][jn][3] - nm1); rs1 += sc[i][jn][3];
            }
            rs0 += __shfl_xor_sync(0xffffffffu, rs0, 1);
            rs0 += __shfl_xor_sync(0xffffffffu, rs0, 2);
            rs1 += __shfl_xor_sync(0xffffffffu, rs1, 1);
            rs1 += __shfl_xor_sync(0xffffffffu, rs1, 2);
            lrow[i][0] = lrow[i][0] * cr0 + rs0;
            lrow[i][1] = lrow[i][1] * cr1 + rs1;
#pragma unroll
            for (int jd = 0; jd < 8; ++jd) {
                o[i][jd][0] *= cr0; o[i][jd][1] *= cr0;
                o[i][jd][2] *= cr1; o[i][jd][3] *= cr1;
            }
#pragma unroll
            for (int kp = 0; kp < 2; ++kp)
#pragma unroll
                for (int rr = 0; rr < 4; ++rr) {
                    int jt = 2 * kp + (rr >> 1);
                    int e  = (rr & 1) * 2;
                    ph[i][kp][rr] = packh(sc[i][jt][e], sc[i][jt][e + 1]);
                }
        }

        // ---- O += P V (p single, v hi/lo) ----
#pragma unroll
        for (int kp = 0; kp < 2; ++kp) {
            int keyr = kb * 32 + kp * 16 + (lane & 15);
#pragma unroll
            for (int g = 0; g < 4; ++g) {
                uint32_t cidx = (uint32_t)(((2 * g + (lane >> 4)) ^ keyr) & 7);
                uint32_t addr = sb + SM_VH + (uint32_t)keyr * 128u + cidx * 16u;
                uint32_t th[4], tl[4];
                ldsm_x4_trans(th, addr);
                ldsm_x4_trans(tl, addr + (SM_VL - SM_VH));
                uint32_t bh0[2] = {th[0], th[1]}, bh1[2] = {th[2], th[3]};
                uint32_t bl0[2] = {tl[0], tl[1]}, bl1[2] = {tl[2], tl[3]};
#pragma unroll
                for (int i = 0; i < 2; ++i) {
                    mma_f16(o[i][2*g],   ph[i][kp], bh0);
                    mma_f16(o[i][2*g],   ph[i][kp], bl0);
                    mma_f16(o[i][2*g+1], ph[i][kp], bh1);
                    mma_f16(o[i][2*g+1], ph[i][kp], bl1);
                }
            }
        }
    }

    // ---- epilogue: normalize and store ----
#pragma unroll
    for (int i = 0; i < 2; ++i) {
        float inv0 = 1.0f / lrow[i][0];
        float inv1 = 1.0f / lrow[i][1];
        int row = q0 + 16 * i + (lane >> 2);
        float* op = out + base + (size_t)row * HH + 2 * (lane & 3);
#pragma unroll
        for (int jd = 0; jd < 8; ++jd) {
            *(float2*)(op + jd * 8) =
                make_float2(o[i][jd][0] * inv0, o[i][jd][1] * inv0);
            *(float2*)(op + 8 * HH + jd * 8) =
                make_float2(o[i][jd][2] * inv1, o[i][jd][3] * inv1);
        }
    }
}

// ---------------------------------------------------------------------------
extern "C" void kernel_launch(void* const* d_in, const int* in_sizes, int n_in,
                              void* d_out, int out_size)
{
    (void)in_sizes; (void)n_in; (void)out_size;
    const float* x  = (const float*)d_in[0];
    const float* Wk = (const float*)d_in[1];
    const float* Wq = (const float*)d_in[2];
    const float* Wv = (const float*)d_in[3];
    float* out = (float*)d_out;

    setup_w16_kernel<<<(6 * 64 * 192 + 255) / 256, 256>>>(Wk, Wq, Wv);

    cudaFuncSetAttribute(qkv_mma_kernel, cudaFuncAttributeMaxDynamicSharedMemorySize,
                         PSM_TOTAL);
    qkv_mma_kernel<<<(BB * TT) / 128, 256, PSM_TOTAL>>>(x);

    cudaFuncSetAttribute(attn_mma_kernel, cudaFuncAttributeMaxDynamicSharedMemorySize,
                         SM_ATT);
    attn_mma_kernel<<<BB, 256, SM_ATT>>>(out);
}